// round 2
// baseline (speedup 1.0000x reference)
#include <cuda_runtime.h>
#include <math.h>

// Problem constants
#define BB 4
#define HH 128
#define WW 128
#define CC 256
#define HEADS 8
#define DD 32
#define NN (HH*WW)          // 16384 tokens per batch
#define MROWS (BB*NN)       // 65536 total rows

// ---------------- scratch (__device__ globals; no allocations allowed) -------------
__device__ float g_q  [(size_t)MROWS*CC];
__device__ float g_k  [(size_t)MROWS*CC];
__device__ float g_v  [(size_t)MROWS*CC];
__device__ float g_tok[(size_t)MROWS*CC];
__device__ float g_y1 [(size_t)MROWS*CC];
__device__ float g_m1 [(size_t)CC*NN];
__device__ float g_m2 [(size_t)CC*NN];
__device__ float g_mf [(size_t)CC*NN];
__device__ float g_npq[64*BB*CC];
__device__ float g_npk[64*BB*CC];
__device__ float g_norm[2*BB*CC];            // [0]=q norms, [1]=k norms
__device__ float g_gp [16*BB*HEADS*DD*DD];   // gram partials [split][bh][i*32+j]
__device__ float g_attn[BB*HEADS*DD*DD];

// ---------------- 128x128-tile, 8x8-microtile, double-buffered SGEMM ---------------
// C[M,N] = A[M,K] * B[K,N] (+bias). biasMode: 0 none, 1 per-col, 2 per-row.
// grid: (N/128, M/128), block: 256. M,N multiples of 128; K multiple of 8; lda%4==0.
__global__ __launch_bounds__(256) void gemm128(
    const float* __restrict__ A, int lda,
    const float* __restrict__ B, int ldb,
    float* __restrict__ C, int ldc,
    const float* __restrict__ bias, int biasMode, int K)
{
    __shared__ float As[2][8][132];   // [buf][k][m] transposed, padded
    __shared__ float Bs[2][8][128];   // [buf][k][n]

    const int tid = threadIdx.x;
    const int row0 = blockIdx.y * 128, col0 = blockIdx.x * 128;

    // compute-thread mapping: 16x16 grid; 8x8 microtile split {t*4, 64+t*4}
    const int tr = tid >> 4;          // 0..15  -> rows tr*4, 64+tr*4
    const int tc = tid & 15;          // 0..15  -> cols tc*4, 64+tc*4

    // global-load mapping
    const int ar  = tid >> 1;                 // A: row within tile (0..127)
    const int ak4 = (tid & 1) * 4;            // A: k offset (0 or 4)
    const int bk  = tid >> 5;                 // B: k row (0..7)
    const int bc4 = (tid & 31) * 4;           // B: col offset (0..124)

    const float* Aptr = A + (size_t)(row0 + ar) * lda + ak4;
    const float* Bptr = B + (size_t)bk * ldb + col0 + bc4;

    float acc[8][8] = {};

    // preload tile 0
    {
        float4 av = *(const float4*)Aptr;
        float4 bv = *(const float4*)Bptr;
        As[0][ak4+0][ar] = av.x; As[0][ak4+1][ar] = av.y;
        As[0][ak4+2][ar] = av.z; As[0][ak4+3][ar] = av.w;
        *(float4*)&Bs[0][bk][bc4] = bv;
    }
    __syncthreads();

    const int NT = K / 8;
    for (int kt = 0; kt < NT; kt++) {
        const int cur = kt & 1, nxt = cur ^ 1;
        float4 av, bv;
        const bool more = (kt + 1 < NT);
        if (more) {
            av = *(const float4*)(Aptr + (size_t)(kt + 1) * 8);
            bv = *(const float4*)(Bptr + (size_t)(kt + 1) * 8 * ldb);
        }
        #pragma unroll
        for (int kk = 0; kk < 8; kk++) {
            float a[8], b[8];
            *(float4*)&a[0] = *(const float4*)&As[cur][kk][tr * 4];
            *(float4*)&a[4] = *(const float4*)&As[cur][kk][64 + tr * 4];
            *(float4*)&b[0] = *(const float4*)&Bs[cur][kk][tc * 4];
            *(float4*)&b[4] = *(const float4*)&Bs[cur][kk][64 + tc * 4];
            #pragma unroll
            for (int i = 0; i < 8; i++)
                #pragma unroll
                for (int j = 0; j < 8; j++)
                    acc[i][j] = fmaf(a[i], b[j], acc[i][j]);
        }
        if (more) {
            As[nxt][ak4+0][ar] = av.x; As[nxt][ak4+1][ar] = av.y;
            As[nxt][ak4+2][ar] = av.z; As[nxt][ak4+3][ar] = av.w;
            *(float4*)&Bs[nxt][bk][bc4] = bv;
            __syncthreads();
        }
    }

    // epilogue: rows {tr*4+i0, 64+tr*4+i0}, cols {tc*4+j0, 64+tc*4+j0}
    #pragma unroll
    for (int ih = 0; ih < 2; ih++) {
        #pragma unroll
        for (int i = 0; i < 4; i++) {
            int r = row0 + ih * 64 + tr * 4 + i;
            float rb = (biasMode == 2) ? bias[r] : 0.f;
            #pragma unroll
            for (int jh = 0; jh < 2; jh++) {
                int cbase = col0 + jh * 64 + tc * 4;
                float4 o;
                float vj[4];
                #pragma unroll
                for (int j = 0; j < 4; j++) {
                    float vv = acc[ih * 4 + i][jh * 4 + j] + rb;
                    if (biasMode == 1) vv += bias[cbase + j];
                    vj[j] = vv;
                }
                o.x = vj[0]; o.y = vj[1]; o.z = vj[2]; o.w = vj[3];
                *(float4*)&C[(size_t)r * ldc + cbase] = o;
            }
        }
    }
}

// ---------------- mask depthwise 5x5 + sigmoid + residual gate ---------------------
// m2,m1,mf layout [C][N]; grid(128=y, 256=c), block 128 (=x)
__global__ __launch_bounds__(128) void mask5(
    const float* __restrict__ m2, const float* __restrict__ m1,
    const float* __restrict__ dw, const float* __restrict__ db,
    float* __restrict__ mf)
{
    int x = threadIdx.x, y = blockIdx.x, c = blockIdx.y;
    __shared__ float ws[25];
    if (x < 25) ws[x] = dw[c * 25 + x];
    __syncthreads();
    float s = db[c];
    const float* mp = m2 + (size_t)c * NN;
    #pragma unroll
    for (int dy = -2; dy <= 2; dy++) {
        int yy = y + dy;
        if (yy < 0 || yy >= HH) continue;
        #pragma unroll
        for (int dx = -2; dx <= 2; dx++) {
            int xx = x + dx;
            if (xx < 0 || xx >= WW) continue;
            s = fmaf(ws[(dy + 2) * 5 + (dx + 2)], mp[yy * WW + xx], s);
        }
    }
    float sig = 1.f / (1.f + expf(-s));
    int p = y * WW + x;
    float a = m1[(size_t)c * NN + p];
    mf[(size_t)c * NN + p] = fmaf(a, sig, a);
}

// ---------------- column L2-norm partials (q and k together) -----------------------
// grid (64 chunks, B), block 256 (=c)
__global__ __launch_bounds__(256) void norm_part(
    const float* __restrict__ q, const float* __restrict__ k,
    float* __restrict__ npq, float* __restrict__ npk)
{
    int chunk = blockIdx.x, b = blockIdx.y, c = threadIdx.x;
    size_t base = ((size_t)b * NN + chunk * 256) * CC + c;
    float sq = 0.f, sk = 0.f;
    #pragma unroll 8
    for (int t = 0; t < 256; t++) {
        float v1 = q[base + (size_t)t * CC]; sq = fmaf(v1, v1, sq);
        float v2 = k[base + (size_t)t * CC]; sk = fmaf(v2, v2, sk);
    }
    int o = (chunk * BB + b) * CC + c;
    npq[o] = sq; npk[o] = sk;
}

// grid (B, 2), block 256
__global__ __launch_bounds__(256) void norm_reduce(
    const float* __restrict__ npq, const float* __restrict__ npk,
    float* __restrict__ gnorm)
{
    int b = blockIdx.x, sel = blockIdx.y, c = threadIdx.x;
    const float* np = sel ? npk : npq;
    float s = 0.f;
    #pragma unroll 8
    for (int ch = 0; ch < 64; ch++) s += np[(ch * BB + b) * CC + c];
    float n = sqrtf(s);
    if (n < 1e-12f) n = 1e-12f;
    gnorm[sel * (BB * CC) + b * CC + c] = n;
}

// ---------------- gram partials: G[b,h,i,j] = sum_n k[...,i] * q[...,j] ------------
// grid (16 splits, 32 bh), block 256
__global__ __launch_bounds__(256) void gram_part(
    const float* __restrict__ q, const float* __restrict__ k,
    float* __restrict__ gp)
{
    __shared__ float Ks[64][33];
    __shared__ float Qs[64][33];
    int sp = blockIdx.x, bh = blockIdx.y;
    int b = bh >> 3, h = bh & 7;
    int tid = threadIdx.x;
    int ii[4], jj[4];
    float acc[4] = {0.f, 0.f, 0.f, 0.f};
    #pragma unroll
    for (int e = 0; e < 4; e++) { int ent = tid + e * 256; ii[e] = ent >> 5; jj[e] = ent & 31; }

    for (int t = 0; t < 16; t++) {
        int n0 = sp * 1024 + t * 64;
        #pragma unroll
        for (int i = 0; i < 8; i++) {
            int idx = tid + i * 256;
            int tok = idx >> 5, j = idx & 31;
            size_t g = ((size_t)b * NN + n0 + tok) * CC + h * DD + j;
            Ks[tok][j] = k[g];
            Qs[tok][j] = q[g];
        }
        __syncthreads();
        #pragma unroll
        for (int kk = 0; kk < 64; kk++) {
            #pragma unroll
            for (int e = 0; e < 4; e++)
                acc[e] = fmaf(Ks[kk][ii[e]], Qs[kk][jj[e]], acc[e]);
        }
        __syncthreads();
    }
    #pragma unroll
    for (int e = 0; e < 4; e++)
        gp[((size_t)(sp * 32 + bh)) * 1024 + tid + e * 256] = acc[e];
}

// ---------------- reduce partials, normalize, rescale, softmax over j --------------
// grid(4), block 256 — one thread per (b,h,i) row
__global__ __launch_bounds__(256) void softmax_k(
    const float* __restrict__ gp, const float* __restrict__ gnorm,
    const float* __restrict__ rescale, float* __restrict__ attn)
{
    int gid = blockIdx.x * 256 + threadIdx.x;
    int b = gid >> 8, rem = gid & 255;
    int h = rem >> 5, i = rem & 31;
    int bh = b * HEADS + h;
    float kn = gnorm[BB * CC + b * CC + h * DD + i];
    float rs = rescale[h];
    float vals[32];
    float mx = -1e30f;
    #pragma unroll
    for (int j = 0; j < 32; j++) {
        float g = 0.f;
        #pragma unroll
        for (int s = 0; s < 16; s++) g += gp[((size_t)(s * 32 + bh)) * 1024 + i * 32 + j];
        float qn = gnorm[b * CC + h * DD + j];
        float val = g / (kn * qn) * rs;
        vals[j] = val;
        mx = fmaxf(mx, val);
    }
    float sum = 0.f;
    #pragma unroll
    for (int j = 0; j < 32; j++) { vals[j] = expf(vals[j] - mx); sum += vals[j]; }
    float inv = 1.f / sum;
    #pragma unroll
    for (int j = 0; j < 32; j++)
        attn[(size_t)bh * 1024 + i * 32 + j] = vals[j] * inv;
}

// ---------------- out_tok[b,n,h*32+i] = sum_j attn[i,j] * (v*mask)[b,n,h*32+j] -----
// grid (128 ntiles, 32 bh), block 128 (= token within tile)
__global__ __launch_bounds__(128) void av_k(
    const float* __restrict__ v, const float* __restrict__ mf,
    const float* __restrict__ attn, float* __restrict__ tok)
{
    __shared__ float At[1024];
    __shared__ float Vs[128][33];
    __shared__ float Ms[32][128];
    int bh = blockIdx.y;
    int b = bh >> 3, h = bh & 7;
    int n0 = blockIdx.x * 128;
    int tid = threadIdx.x;

    #pragma unroll
    for (int i = 0; i < 8; i++) At[tid + i * 128] = attn[(size_t)bh * 1024 + tid + i * 128];
    #pragma unroll
    for (int i = 0; i < 32; i++) {
        int idx = tid + i * 128;
        int tk = idx >> 5, j = idx & 31;
        Vs[tk][j] = v[((size_t)b * NN + n0 + tk) * CC + h * DD + j];
        int jm = idx >> 7, tm = idx & 127;
        Ms[jm][tm] = mf[(size_t)(h * DD + jm) * NN + n0 + tm];
    }
    __syncthreads();

    int t = tid;
    float vm[32];
    #pragma unroll
    for (int j = 0; j < 32; j++) vm[j] = Vs[t][j] * Ms[j][t];
    size_t obase = ((size_t)b * NN + n0 + t) * CC + h * DD;
    #pragma unroll
    for (int i = 0; i < 32; i++) {
        float o = 0.f;
        #pragma unroll
        for (int j = 0; j < 32; j++) o = fmaf(At[i * 32 + j], vm[j], o);
        tok[obase + i] = o;
    }
}

// ---------------- depthwise 3x3 (pad=1), rolling register window -------------------
// layout [b,n,c] (c fastest). grid(128=y, B), block 256 (=c)
// mode 0: out = gelu_exact(conv(in));  mode 1: out += conv(in)
__global__ __launch_bounds__(256) void dw3x3_k(
    const float* __restrict__ in, const float* __restrict__ w9,
    float* __restrict__ out, int mode)
{
    __shared__ float ws[9 * CC];
    int c = threadIdx.x;
    int y = blockIdx.x, b = blockIdx.y;
    #pragma unroll
    for (int i = 0; i < 9; i++) ws[c + i * CC] = w9[c + i * CC];  // staging copy
    __syncthreads();
    float wv[9];
    #pragma unroll
    for (int t = 0; t < 9; t++) wv[t] = ws[c * 9 + t];

    const size_t base = (size_t)b * NN * CC + c;
    float a[3][3];
    #pragma unroll
    for (int r = 0; r < 3; r++) {
        int yy = y - 1 + r;
        bool yok = (yy >= 0 && yy < HH);
        a[r][0] = 0.f;
        a[r][1] = yok ? in[base + (size_t)(yy * WW + 0) * CC] : 0.f;
        a[r][2] = yok ? in[base + (size_t)(yy * WW + 1) * CC] : 0.f;
    }
    for (int x = 0; x < WW; x++) {
        float acc = 0.f;
        #pragma unroll
        for (int r = 0; r < 3; r++)
            #pragma unroll
            for (int k2 = 0; k2 < 3; k2++)
                acc = fmaf(wv[r * 3 + k2], a[r][k2], acc);
        size_t o = base + (size_t)(y * WW + x) * CC;
        if (mode == 0) {
            acc = 0.5f * acc * (1.f + erff(acc * 0.70710678118654752f));
            out[o] = acc;
        } else {
            out[o] += acc;
        }
        int xn = x + 2;
        bool xok = (xn < WW);
        #pragma unroll
        for (int r = 0; r < 3; r++) {
            int yy = y - 1 + r;
            bool ok = xok && (yy >= 0 && yy < HH);
            a[r][0] = a[r][1];
            a[r][1] = a[r][2];
            a[r][2] = ok ? in[base + (size_t)(yy * WW + xn) * CC] : 0.f;
        }
    }
}

// ================================= launch ==========================================
extern "C" void kernel_launch(void* const* d_in, const int* in_sizes, int n_in,
                              void* d_out, int out_size)
{
    const float* x      = (const float*)d_in[0];
    const float* mask   = (const float*)d_in[1];
    const float* wq     = (const float*)d_in[2];
    const float* wk     = (const float*)d_in[3];
    const float* wv     = (const float*)d_in[4];
    const float* rescale= (const float*)d_in[5];
    const float* wproj  = (const float*)d_in[6];
    const float* bproj  = (const float*)d_in[7];
    const float* mg_w1  = (const float*)d_in[8];
    const float* mg_b1  = (const float*)d_in[9];
    const float* mg_w2  = (const float*)d_in[10];
    const float* mg_b2  = (const float*)d_in[11];
    const float* mg_dw  = (const float*)d_in[12];
    const float* mg_db  = (const float*)d_in[13];
    const float* be_w1  = (const float*)d_in[14];
    const float* be_w2  = (const float*)d_in[15];
    float* out = (float*)d_out;

    float *q, *k, *v, *tok, *y1, *m1, *m2, *mf, *npq, *npk, *gnorm, *gp, *attn;
    cudaGetSymbolAddress((void**)&q,    g_q);
    cudaGetSymbolAddress((void**)&k,    g_k);
    cudaGetSymbolAddress((void**)&v,    g_v);
    cudaGetSymbolAddress((void**)&tok,  g_tok);
    cudaGetSymbolAddress((void**)&y1,   g_y1);
    cudaGetSymbolAddress((void**)&m1,   g_m1);
    cudaGetSymbolAddress((void**)&m2,   g_m2);
    cudaGetSymbolAddress((void**)&mf,   g_mf);
    cudaGetSymbolAddress((void**)&npq,  g_npq);
    cudaGetSymbolAddress((void**)&npk,  g_npk);
    cudaGetSymbolAddress((void**)&gnorm,g_norm);
    cudaGetSymbolAddress((void**)&gp,   g_gp);
    cudaGetSymbolAddress((void**)&attn, g_attn);

    // q/k/v projections: [65536,256] @ [256,256]
    gemm128<<<dim3(CC / 128, MROWS / 128), 256>>>(x, CC, wq, CC, q, CC, nullptr, 0, CC);
    gemm128<<<dim3(CC / 128, MROWS / 128), 256>>>(x, CC, wk, CC, k, CC, nullptr, 0, CC);
    gemm128<<<dim3(CC / 128, MROWS / 128), 256>>>(x, CC, wv, CC, v, CC, nullptr, 0, CC);

    // mask-guided: m1 = W1 @ mask + b1 ; m2 = W2 @ m1 + b2   ([C,C] @ [C,N])
    gemm128<<<dim3(NN / 128, CC / 128), 256>>>(mg_w1, CC, mask, NN, m1, NN, mg_b1, 2, CC);
    gemm128<<<dim3(NN / 128, CC / 128), 256>>>(mg_w2, CC, m1, NN, m2, NN, mg_b2, 2, CC);
    mask5<<<dim3(HH, CC), 128>>>(m2, m1, mg_dw, mg_db, mf);

    // per-channel L2 norms over token dim (deterministic two-stage)
    norm_part<<<dim3(64, BB), 256>>>(q, k, npq, npk);
    norm_reduce<<<dim3(BB, 2), 256>>>(npq, npk, gnorm);

    // gram + softmax
    gram_part<<<dim3(16, BB * HEADS), 256>>>(q, k, gp);
    softmax_k<<<4, 256>>>(gp, gnorm, rescale, attn);

    // out_tok = attn @ (v * mask_emb)
    av_k<<<dim3(NN / 128, BB * HEADS), 128>>>(v, mf, attn, tok);

    // projection into d_out
    gemm128<<<dim3(CC / 128, MROWS / 128), 256>>>(tok, CC, wproj, CC, out, CC, bproj, 1, CC);

    // band_emb: dw3x3 -> GELU -> dw3x3, added into d_out
    dw3x3_k<<<dim3(HH, BB), 256>>>(v, be_w1, y1, 0);
    dw3x3_k<<<dim3(HH, BB), 256>>>(y1, be_w2, out, 1);
}

// round 5
// speedup vs baseline: 1.0403x; 1.0403x over previous
#include <cuda_runtime.h>
#include <cuda_bf16.h>
#include <stdint.h>
#include <math.h>

// Problem constants
#define BB 4
#define HH 128
#define WW 128
#define CC 256
#define HEADS 8
#define DD 32
#define NN (HH*WW)          // 16384 tokens per batch
#define MROWS (BB*NN)       // 65536 total rows
#define KDIM 256

// ---------------- scratch (__device__ globals; no allocations allowed) -------------
__device__ float g_q  [(size_t)MROWS*CC];
__device__ float g_k  [(size_t)MROWS*CC];
__device__ float g_v  [(size_t)MROWS*CC];
__device__ float g_y1 [(size_t)MROWS*CC];
__device__ float g_m1 [(size_t)CC*NN];
__device__ float g_m2 [(size_t)CC*NN];
__device__ float g_mf [(size_t)CC*NN];
__device__ float g_npq[64*BB*CC];
__device__ float g_npk[64*BB*CC];
__device__ float g_norm[2*BB*CC];            // [0]=q norms, [1]=k norms
__device__ float g_gp [16*BB*HEADS*DD*DD];   // gram partials
__device__ float g_attn[BB*HEADS*DD*DD];

__device__ __nv_bfloat16 g_xhi [(size_t)MROWS*CC];
__device__ __nv_bfloat16 g_xlo [(size_t)MROWS*CC];
__device__ __nv_bfloat16 g_tokhi[(size_t)MROWS*CC];
__device__ __nv_bfloat16 g_toklo[(size_t)MROWS*CC];
__device__ __nv_bfloat16 g_wqkvh[768*256];   // Bt[n][k] hi
__device__ __nv_bfloat16 g_wqkvl[768*256];
__device__ __nv_bfloat16 g_wph  [256*256];
__device__ __nv_bfloat16 g_wpl  [256*256];

// ---------------- fp32 -> bf16 hi/lo split -----------------------------------------
__global__ __launch_bounds__(256) void split_bf16(
    const float* __restrict__ in, __nv_bfloat16* __restrict__ hi,
    __nv_bfloat16* __restrict__ lo)
{
    size_t i = ((size_t)blockIdx.x * 256 + threadIdx.x) * 4;
    float4 v = *(const float4*)(in + i);
    __nv_bfloat16 h0 = __float2bfloat16(v.x);
    __nv_bfloat16 h1 = __float2bfloat16(v.y);
    __nv_bfloat16 h2 = __float2bfloat16(v.z);
    __nv_bfloat16 h3 = __float2bfloat16(v.w);
    __nv_bfloat162 hp0; hp0.x = h0; hp0.y = h1;
    __nv_bfloat162 hp1; hp1.x = h2; hp1.y = h3;
    *(__nv_bfloat162*)(hi + i)     = hp0;
    *(__nv_bfloat162*)(hi + i + 2) = hp1;
    __nv_bfloat162 lp0, lp1;
    lp0.x = __float2bfloat16(v.x - __bfloat162float(h0));
    lp0.y = __float2bfloat16(v.y - __bfloat162float(h1));
    lp1.x = __float2bfloat16(v.z - __bfloat162float(h2));
    lp1.y = __float2bfloat16(v.w - __bfloat162float(h3));
    *(__nv_bfloat162*)(lo + i)     = lp0;
    *(__nv_bfloat162*)(lo + i + 2) = lp1;
}

// ---------------- pack weights transposed: Bt[n][k] = W[k][n], split hi/lo ---------
// grid 768 (n), block 256 (k): seg = n>>8 selects wq/wk/wv
__global__ __launch_bounds__(256) void pack_wqkv(
    const float* __restrict__ wq, const float* __restrict__ wk,
    const float* __restrict__ wv,
    __nv_bfloat16* __restrict__ bh, __nv_bfloat16* __restrict__ bl)
{
    int n = blockIdx.x, k = threadIdx.x;
    int seg = n >> 8, lc = n & 255;
    const float* w = (seg == 0) ? wq : (seg == 1) ? wk : wv;
    float v = w[k * 256 + lc];
    __nv_bfloat16 h = __float2bfloat16(v);
    bh[n * 256 + k] = h;
    bl[n * 256 + k] = __float2bfloat16(v - __bfloat162float(h));
}

__global__ __launch_bounds__(256) void pack_w1(
    const float* __restrict__ w,
    __nv_bfloat16* __restrict__ bh, __nv_bfloat16* __restrict__ bl)
{
    int n = blockIdx.x, k = threadIdx.x;
    float v = w[k * 256 + n];
    __nv_bfloat16 h = __float2bfloat16(v);
    bh[n * 256 + k] = h;
    bl[n * 256 + k] = __float2bfloat16(v - __bfloat162float(h));
}

// ---------------- bf16 split-3 tensor-core GEMM ------------------------------------
// C[M,768 or 256] = A[M,256] @ B[256,N]; A as hi/lo bf16 [M][256] row-major,
// B as Bt hi/lo bf16 [N][256] (n-major). Out fp32 routed per 256-col segment.
// grid (N/64, M/128), block 256 (8 warps, 4x2 warp grid, 32x32 warp tile).
#define MMA_BF16(d, a, b) \
  asm volatile("mma.sync.aligned.m16n8k16.row.col.f32.bf16.bf16.f32 " \
      "{%0,%1,%2,%3}, {%4,%5,%6,%7}, {%8,%9}, {%0,%1,%2,%3};" \
      : "+f"(d[0]), "+f"(d[1]), "+f"(d[2]), "+f"(d[3]) \
      : "r"(a[0]), "r"(a[1]), "r"(a[2]), "r"(a[3]), "r"(b[0]), "r"(b[1]))

// smem element offsets (bf16): rows padded to 40 elements (80B) => conflict-free frags
#define APAD 40
#define ABUF (128*APAD)     // 5120
#define BBUF (64*APAD)      // 2560

__global__ __launch_bounds__(256) void mmagemm(
    const __nv_bfloat16* __restrict__ Ahi, const __nv_bfloat16* __restrict__ Alo,
    const __nv_bfloat16* __restrict__ Bth, const __nv_bfloat16* __restrict__ Btl,
    float* C0, float* C1, float* C2, const float* __restrict__ bias)
{
    extern __shared__ __align__(16) __nv_bfloat16 sm[];
    __nv_bfloat16* AsH = sm;                       // [2][ABUF]
    __nv_bfloat16* AsL = sm + 2 * ABUF;
    __nv_bfloat16* BsH = sm + 4 * ABUF;            // [2][BBUF]
    __nv_bfloat16* BsL = sm + 4 * ABUF + 2 * BBUF;

    const int tid = threadIdx.x;
    const int lane = tid & 31, warp = tid >> 5;
    const int g = lane >> 2, q = lane & 3;
    const int wm = (warp >> 1) * 32, wn = (warp & 1) * 32;
    const int row0 = blockIdx.y * 128;
    const int colg = blockIdx.x * 64;

    // loader mapping
    const int arow = tid >> 2, aseg = tid & 3;     // used with j offsets for A
    float acc[2][4][4] = {};

    uint4 rah[2], ral[2], rbh, rbl;
    // preload chunk 0
    {
        #pragma unroll
        for (int j = 0; j < 2; j++) {
            int idx = tid + j * 256;
            int r = idx >> 2, s = idx & 3;
            size_t go = (size_t)(row0 + r) * KDIM + s * 8;
            rah[j] = *(const uint4*)(Ahi + go);
            ral[j] = *(const uint4*)(Alo + go);
        }
        size_t gb = (size_t)(colg + arow) * KDIM + aseg * 8;
        rbh = *(const uint4*)(Bth + gb);
        rbl = *(const uint4*)(Btl + gb);
        #pragma unroll
        for (int j = 0; j < 2; j++) {
            int idx = tid + j * 256;
            int r = idx >> 2, s = idx & 3;
            *(uint4*)(AsH + r * APAD + s * 8) = rah[j];
            *(uint4*)(AsL + r * APAD + s * 8) = ral[j];
        }
        *(uint4*)(BsH + arow * APAD + aseg * 8) = rbh;
        *(uint4*)(BsL + arow * APAD + aseg * 8) = rbl;
    }
    __syncthreads();

    #pragma unroll 1
    for (int kt = 0; kt < 8; kt++) {
        const int buf = kt & 1;
        const bool more = (kt < 7);
        if (more) {
            int kc = (kt + 1) * 32;
            #pragma unroll
            for (int j = 0; j < 2; j++) {
                int idx = tid + j * 256;
                int r = idx >> 2, s = idx & 3;
                size_t go = (size_t)(row0 + r) * KDIM + kc + s * 8;
                rah[j] = *(const uint4*)(Ahi + go);
                ral[j] = *(const uint4*)(Alo + go);
            }
            size_t gb = (size_t)(colg + arow) * KDIM + kc + aseg * 8;
            rbh = *(const uint4*)(Bth + gb);
            rbl = *(const uint4*)(Btl + gb);
        }

        const __nv_bfloat16* aH = AsH + buf * ABUF;
        const __nv_bfloat16* aL = AsL + buf * ABUF;
        const __nv_bfloat16* bH = BsH + buf * BBUF;
        const __nv_bfloat16* bL = BsL + buf * BBUF;

        #pragma unroll
        for (int ki = 0; ki < 2; ki++) {
            uint32_t ah[2][4], al[2][4], bh[4][2], bl[4][2];
            const int kb = ki * 16 + 2 * q;
            #pragma unroll
            for (int mi = 0; mi < 2; mi++) {
                int r = wm + mi * 16 + g;
                ah[mi][0] = *(const uint32_t*)(aH + r * APAD + kb);
                ah[mi][1] = *(const uint32_t*)(aH + (r + 8) * APAD + kb);
                ah[mi][2] = *(const uint32_t*)(aH + r * APAD + kb + 8);
                ah[mi][3] = *(const uint32_t*)(aH + (r + 8) * APAD + kb + 8);
                al[mi][0] = *(const uint32_t*)(aL + r * APAD + kb);
                al[mi][1] = *(const uint32_t*)(aL + (r + 8) * APAD + kb);
                al[mi][2] = *(const uint32_t*)(aL + r * APAD + kb + 8);
                al[mi][3] = *(const uint32_t*)(aL + (r + 8) * APAD + kb + 8);
            }
            #pragma unroll
            for (int ni = 0; ni < 4; ni++) {
                int n = wn + ni * 8 + g;
                bh[ni][0] = *(const uint32_t*)(bH + n * APAD + kb);
                bh[ni][1] = *(const uint32_t*)(bH + n * APAD + kb + 8);
                bl[ni][0] = *(const uint32_t*)(bL + n * APAD + kb);
                bl[ni][1] = *(const uint32_t*)(bL + n * APAD + kb + 8);
            }
            #pragma unroll
            for (int mi = 0; mi < 2; mi++)
                #pragma unroll
                for (int ni = 0; ni < 4; ni++) {
                    MMA_BF16(acc[mi][ni], ah[mi], bh[ni]);
                    MMA_BF16(acc[mi][ni], ah[mi], bl[ni]);
                    MMA_BF16(acc[mi][ni], al[mi], bh[ni]);
                }
        }

        if (more) {
            __syncthreads();
            const int nb = (kt + 1) & 1;
            #pragma unroll
            for (int j = 0; j < 2; j++) {
                int idx = tid + j * 256;
                int r = idx >> 2, s = idx & 3;
                *(uint4*)(AsH + nb * ABUF + r * APAD + s * 8) = rah[j];
                *(uint4*)(AsL + nb * ABUF + r * APAD + s * 8) = ral[j];
            }
            *(uint4*)(BsH + nb * BBUF + arow * APAD + aseg * 8) = rbh;
            *(uint4*)(BsL + nb * BBUF + arow * APAD + aseg * 8) = rbl;
            __syncthreads();
        }
    }

    // epilogue: route per 256-col segment
    const int seg = colg >> 8;
    float* outp = (seg == 0) ? C0 : (seg == 1) ? C1 : C2;
    const int lcol0 = (colg & 255) + wn;
    #pragma unroll
    for (int mi = 0; mi < 2; mi++) {
        int r0 = row0 + wm + mi * 16 + g;
        #pragma unroll
        for (int ni = 0; ni < 4; ni++) {
            int lc = lcol0 + ni * 8 + 2 * q;
            float b0 = 0.f, b1 = 0.f;
            if (bias) { b0 = bias[lc]; b1 = bias[lc + 1]; }
            float2 s0 = make_float2(acc[mi][ni][0] + b0, acc[mi][ni][1] + b1);
            float2 s1 = make_float2(acc[mi][ni][2] + b0, acc[mi][ni][3] + b1);
            *(float2*)(outp + (size_t)r0 * 256 + lc)       = s0;
            *(float2*)(outp + (size_t)(r0 + 8) * 256 + lc) = s1;
        }
    }
}

// ---------------- fp32 SGEMM (kept for mask path) ----------------------------------
__global__ __launch_bounds__(256) void gemm128(
    const float* __restrict__ A, int lda,
    const float* __restrict__ B, int ldb,
    float* __restrict__ C, int ldc,
    const float* __restrict__ bias, int biasMode, int K)
{
    __shared__ float As[2][8][132];
    __shared__ float Bs[2][8][128];
    const int tid = threadIdx.x;
    const int row0 = blockIdx.y * 128, col0 = blockIdx.x * 128;
    const int tr = tid >> 4, tc = tid & 15;
    const int ar  = tid >> 1, ak4 = (tid & 1) * 4;
    const int bk  = tid >> 5, bc4 = (tid & 31) * 4;
    const float* Aptr = A + (size_t)(row0 + ar) * lda + ak4;
    const float* Bptr = B + (size_t)bk * ldb + col0 + bc4;
    float acc[8][8] = {};
    {
        float4 av = *(const float4*)Aptr;
        float4 bv = *(const float4*)Bptr;
        As[0][ak4+0][ar] = av.x; As[0][ak4+1][ar] = av.y;
        As[0][ak4+2][ar] = av.z; As[0][ak4+3][ar] = av.w;
        *(float4*)&Bs[0][bk][bc4] = bv;
    }
    __syncthreads();
    const int NT = K / 8;
    for (int kt = 0; kt < NT; kt++) {
        const int cur = kt & 1, nxt = cur ^ 1;
        float4 av, bv;
        const bool more = (kt + 1 < NT);
        if (more) {
            av = *(const float4*)(Aptr + (size_t)(kt + 1) * 8);
            bv = *(const float4*)(Bptr + (size_t)(kt + 1) * 8 * ldb);
        }
        #pragma unroll
        for (int kk = 0; kk < 8; kk++) {
            float a[8], b[8];
            *(float4*)&a[0] = *(const float4*)&As[cur][kk][tr * 4];
            *(float4*)&a[4] = *(const float4*)&As[cur][kk][64 + tr * 4];
            *(float4*)&b[0] = *(const float4*)&Bs[cur][kk][tc * 4];
            *(float4*)&b[4] = *(const float4*)&Bs[cur][kk][64 + tc * 4];
            #pragma unroll
            for (int i = 0; i < 8; i++)
                #pragma unroll
                for (int j = 0; j < 8; j++)
                    acc[i][j] = fmaf(a[i], b[j], acc[i][j]);
        }
        if (more) {
            As[nxt][ak4+0][ar] = av.x; As[nxt][ak4+1][ar] = av.y;
            As[nxt][ak4+2][ar] = av.z; As[nxt][ak4+3][ar] = av.w;
            *(float4*)&Bs[nxt][bk][bc4] = bv;
            __syncthreads();
        }
    }
    #pragma unroll
    for (int ih = 0; ih < 2; ih++)
        #pragma unroll
        for (int i = 0; i < 4; i++) {
            int r = row0 + ih * 64 + tr * 4 + i;
            float rb = (biasMode == 2) ? bias[r] : 0.f;
            #pragma unroll
            for (int jh = 0; jh < 2; jh++) {
                int cbase = col0 + jh * 64 + tc * 4;
                float vj[4];
                #pragma unroll
                for (int j = 0; j < 4; j++) {
                    float vv = acc[ih * 4 + i][jh * 4 + j] + rb;
                    if (biasMode == 1) vv += bias[cbase + j];
                    vj[j] = vv;
                }
                float4 o; o.x = vj[0]; o.y = vj[1]; o.z = vj[2]; o.w = vj[3];
                *(float4*)&C[(size_t)r * ldc + cbase] = o;
            }
        }
}

// ---------------- mask depthwise 5x5 + sigmoid + residual gate ---------------------
__global__ __launch_bounds__(128) void mask5(
    const float* __restrict__ m2, const float* __restrict__ m1,
    const float* __restrict__ dw, const float* __restrict__ db,
    float* __restrict__ mf)
{
    int x = threadIdx.x, y = blockIdx.x, c = blockIdx.y;
    __shared__ float ws[25];
    if (x < 25) ws[x] = dw[c * 25 + x];
    __syncthreads();
    float s = db[c];
    const float* mp = m2 + (size_t)c * NN;
    #pragma unroll
    for (int dy = -2; dy <= 2; dy++) {
        int yy = y + dy;
        if (yy < 0 || yy >= HH) continue;
        #pragma unroll
        for (int dx = -2; dx <= 2; dx++) {
            int xx = x + dx;
            if (xx < 0 || xx >= WW) continue;
            s = fmaf(ws[(dy + 2) * 5 + (dx + 2)], mp[yy * WW + xx], s);
        }
    }
    float sig = 1.f / (1.f + expf(-s));
    int p = y * WW + x;
    float a = m1[(size_t)c * NN + p];
    mf[(size_t)c * NN + p] = fmaf(a, sig, a);
}

// ---------------- column L2-norm partials ------------------------------------------
__global__ __launch_bounds__(256) void norm_part(
    const float* __restrict__ q, const float* __restrict__ k,
    float* __restrict__ npq, float* __restrict__ npk)
{
    int chunk = blockIdx.x, b = blockIdx.y, c = threadIdx.x;
    size_t base = ((size_t)b * NN + chunk * 256) * CC + c;
    float sq = 0.f, sk = 0.f;
    #pragma unroll 8
    for (int t = 0; t < 256; t++) {
        float v1 = q[base + (size_t)t * CC]; sq = fmaf(v1, v1, sq);
        float v2 = k[base + (size_t)t * CC]; sk = fmaf(v2, v2, sk);
    }
    int o = (chunk * BB + b) * CC + c;
    npq[o] = sq; npk[o] = sk;
}

__global__ __launch_bounds__(256) void norm_reduce(
    const float* __restrict__ npq, const float* __restrict__ npk,
    float* __restrict__ gnorm)
{
    int b = blockIdx.x, sel = blockIdx.y, c = threadIdx.x;
    const float* np = sel ? npk : npq;
    float s = 0.f;
    #pragma unroll 8
    for (int ch = 0; ch < 64; ch++) s += np[(ch * BB + b) * CC + c];
    float n = sqrtf(s);
    if (n < 1e-12f) n = 1e-12f;
    gnorm[sel * (BB * CC) + b * CC + c] = n;
}

// ---------------- gram partials ----------------------------------------------------
__global__ __launch_bounds__(256) void gram_part(
    const float* __restrict__ q, const float* __restrict__ k,
    float* __restrict__ gp)
{
    __shared__ float Ks[64][33];
    __shared__ float Qs[64][33];
    int sp = blockIdx.x, bh = blockIdx.y;
    int b = bh >> 3, h = bh & 7;
    int tid = threadIdx.x;
    int ii[4], jj[4];
    float acc[4] = {0.f, 0.f, 0.f, 0.f};
    #pragma unroll
    for (int e = 0; e < 4; e++) { int ent = tid + e * 256; ii[e] = ent >> 5; jj[e] = ent & 31; }
    for (int t = 0; t < 16; t++) {
        int n0 = sp * 1024 + t * 64;
        #pragma unroll
        for (int i = 0; i < 8; i++) {
            int idx = tid + i * 256;
            int tok = idx >> 5, j = idx & 31;
            size_t g = ((size_t)b * NN + n0 + tok) * CC + h * DD + j;
            Ks[tok][j] = k[g];
            Qs[tok][j] = q[g];
        }
        __syncthreads();
        #pragma unroll
        for (int kk = 0; kk < 64; kk++) {
            #pragma unroll
            for (int e = 0; e < 4; e++)
                acc[e] = fmaf(Ks[kk][ii[e]], Qs[kk][jj[e]], acc[e]);
        }
        __syncthreads();
    }
    #pragma unroll
    for (int e = 0; e < 4; e++)
        gp[((size_t)(sp * 32 + bh)) * 1024 + tid + e * 256] = acc[e];
}

// ---------------- softmax over gram ------------------------------------------------
__global__ __launch_bounds__(256) void softmax_k(
    const float* __restrict__ gp, const float* __restrict__ gnorm,
    const float* __restrict__ rescale, float* __restrict__ attn)
{
    int gid = blockIdx.x * 256 + threadIdx.x;
    int b = gid >> 8, rem = gid & 255;
    int h = rem >> 5, i = rem & 31;
    int bh = b * HEADS + h;
    float kn = gnorm[BB * CC + b * CC + h * DD + i];
    float rs = rescale[h];
    float vals[32];
    float mx = -1e30f;
    #pragma unroll
    for (int j = 0; j < 32; j++) {
        float g = 0.f;
        #pragma unroll
        for (int s = 0; s < 16; s++) g += gp[((size_t)(s * 32 + bh)) * 1024 + i * 32 + j];
        float qn = gnorm[b * CC + h * DD + j];
        float val = g / (kn * qn) * rs;
        vals[j] = val;
        mx = fmaxf(mx, val);
    }
    float sum = 0.f;
    #pragma unroll
    for (int j = 0; j < 32; j++) { vals[j] = expf(vals[j] - mx); sum += vals[j]; }
    float inv = 1.f / sum;
    #pragma unroll
    for (int j = 0; j < 32; j++)
        attn[(size_t)bh * 1024 + i * 32 + j] = vals[j] * inv;
}

// ---------------- out_tok = attn @ (v*mask), emitted as bf16 hi/lo -----------------
__global__ __launch_bounds__(128) void av_k(
    const float* __restrict__ v, const float* __restrict__ mf,
    const float* __restrict__ attn,
    __nv_bfloat16* __restrict__ tokhi, __nv_bfloat16* __restrict__ toklo)
{
    __shared__ float At[1024];
    __shared__ float Vs[128][33];
    __shared__ float Ms[32][128];
    int bh = blockIdx.y;
    int b = bh >> 3, h = bh & 7;
    int n0 = blockIdx.x * 128;
    int tid = threadIdx.x;
    #pragma unroll
    for (int i = 0; i < 8; i++) At[tid + i * 128] = attn[(size_t)bh * 1024 + tid + i * 128];
    #pragma unroll
    for (int i = 0; i < 32; i++) {
        int idx = tid + i * 128;
        int tk = idx >> 5, j = idx & 31;
        Vs[tk][j] = v[((size_t)b * NN + n0 + tk) * CC + h * DD + j];
        int jm = idx >> 7, tm = idx & 127;
        Ms[jm][tm] = mf[(size_t)(h * DD + jm) * NN + n0 + tm];
    }
    __syncthreads();
    int t = tid;
    float vm[32];
    #pragma unroll
    for (int j = 0; j < 32; j++) vm[j] = Vs[t][j] * Ms[j][t];
    size_t obase = ((size_t)b * NN + n0 + t) * CC + h * DD;
    #pragma unroll
    for (int i = 0; i < 32; i++) {
        float o = 0.f;
        #pragma unroll
        for (int j = 0; j < 32; j++) o = fmaf(At[i * 32 + j], vm[j], o);
        __nv_bfloat16 hi = __float2bfloat16(o);
        tokhi[obase + i] = hi;
        toklo[obase + i] = __float2bfloat16(o - __bfloat162float(hi));
    }
}

// ---------------- depthwise 3x3 (pad=1), rolling register window -------------------
__global__ __launch_bounds__(256) void dw3x3_k(
    const float* __restrict__ in, const float* __restrict__ w9,
    float* __restrict__ out, int mode)
{
    __shared__ float ws[9 * CC];
    int c = threadIdx.x;
    int y = blockIdx.x, b = blockIdx.y;
    #pragma unroll
    for (int i = 0; i < 9; i++) ws[c + i * CC] = w9[c + i * CC];
    __syncthreads();
    float wv[9];
    #pragma unroll
    for (int t = 0; t < 9; t++) wv[t] = ws[c * 9 + t];
    const size_t base = (size_t)b * NN * CC + c;
    float a[3][3];
    #pragma unroll
    for (int r = 0; r < 3; r++) {
        int yy = y - 1 + r;
        bool yok = (yy >= 0 && yy < HH);
        a[r][0] = 0.f;
        a[r][1] = yok ? in[base + (size_t)(yy * WW + 0) * CC] : 0.f;
        a[r][2] = yok ? in[base + (size_t)(yy * WW + 1) * CC] : 0.f;
    }
    for (int x = 0; x < WW; x++) {
        float acc = 0.f;
        #pragma unroll
        for (int r = 0; r < 3; r++)
            #pragma unroll
            for (int k2 = 0; k2 < 3; k2++)
                acc = fmaf(wv[r * 3 + k2], a[r][k2], acc);
        size_t o = base + (size_t)(y * WW + x) * CC;
        if (mode == 0) {
            acc = 0.5f * acc * (1.f + erff(acc * 0.70710678118654752f));
            out[o] = acc;
        } else {
            out[o] += acc;
        }
        int xn = x + 2;
        bool xok = (xn < WW);
        #pragma unroll
        for (int r = 0; r < 3; r++) {
            int yy = y - 1 + r;
            bool ok = xok && (yy >= 0 && yy < HH);
            a[r][0] = a[r][1];
            a[r][1] = a[r][2];
            a[r][2] = ok ? in[base + (size_t)(yy * WW + xn) * CC] : 0.f;
        }
    }
}

// ================================= launch ==========================================
extern "C" void kernel_launch(void* const* d_in, const int* in_sizes, int n_in,
                              void* d_out, int out_size)
{
    const float* x      = (const float*)d_in[0];
    const float* mask   = (const float*)d_in[1];
    const float* wq     = (const float*)d_in[2];
    const float* wk     = (const float*)d_in[3];
    const float* wv     = (const float*)d_in[4];
    const float* rescale= (const float*)d_in[5];
    const float* wproj  = (const float*)d_in[6];
    const float* bproj  = (const float*)d_in[7];
    const float* mg_w1  = (const float*)d_in[8];
    const float* mg_b1  = (const float*)d_in[9];
    const float* mg_w2  = (const float*)d_in[10];
    const float* mg_b2  = (const float*)d_in[11];
    const float* mg_dw  = (const float*)d_in[12];
    const float* mg_db  = (const float*)d_in[13];
    const float* be_w1  = (const float*)d_in[14];
    const float* be_w2  = (const float*)d_in[15];
    float* out = (float*)d_out;

    float *q, *k, *v, *y1, *m1, *m2, *mf, *npq, *npk, *gnorm, *gp, *attn;
    __nv_bfloat16 *xhi, *xlo, *tokhi, *toklo, *wqkvh, *wqkvl, *wph, *wpl;
    cudaGetSymbolAddress((void**)&q,    g_q);
    cudaGetSymbolAddress((void**)&k,    g_k);
    cudaGetSymbolAddress((void**)&v,    g_v);
    cudaGetSymbolAddress((void**)&y1,   g_y1);
    cudaGetSymbolAddress((void**)&m1,   g_m1);
    cudaGetSymbolAddress((void**)&m2,   g_m2);
    cudaGetSymbolAddress((void**)&mf,   g_mf);
    cudaGetSymbolAddress((void**)&npq,  g_npq);
    cudaGetSymbolAddress((void**)&npk,  g_npk);
    cudaGetSymbolAddress((void**)&gnorm,g_norm);
    cudaGetSymbolAddress((void**)&gp,   g_gp);
    cudaGetSymbolAddress((void**)&attn, g_attn);
    cudaGetSymbolAddress((void**)&xhi,  g_xhi);
    cudaGetSymbolAddress((void**)&xlo,  g_xlo);
    cudaGetSymbolAddress((void**)&tokhi,g_tokhi);
    cudaGetSymbolAddress((void**)&toklo,g_toklo);
    cudaGetSymbolAddress((void**)&wqkvh,g_wqkvh);
    cudaGetSymbolAddress((void**)&wqkvl,g_wqkvl);
    cudaGetSymbolAddress((void**)&wph,  g_wph);
    cudaGetSymbolAddress((void**)&wpl,  g_wpl);

    const int MMASMEM = (4 * ABUF + 4 * BBUF) * 2;   // 61440 bytes
    cudaFuncSetAttribute(mmagemm, cudaFuncAttributeMaxDynamicSharedMemorySize, MMASMEM);

    // prep: split x; pack weights
    split_bf16<<<(MROWS * CC) / 1024, 256>>>(x, xhi, xlo);
    pack_wqkv<<<768, 256>>>(wq, wk, wv, wqkvh, wqkvl);
    pack_w1<<<256, 256>>>(wproj, wph, wpl);

    // fused qkv tensor-core GEMM: [65536,256] @ [256,768] -> q,k,v
    mmagemm<<<dim3(12, MROWS / 128), 256, MMASMEM>>>(xhi, xlo, wqkvh, wqkvl, q, k, v, nullptr);

    // mask-guided path (fp32 SGEMM)
    gemm128<<<dim3(NN / 128, CC / 128), 256>>>(mg_w1, CC, mask, NN, m1, NN, mg_b1, 2, CC);
    gemm128<<<dim3(NN / 128, CC / 128), 256>>>(mg_w2, CC, m1, NN, m2, NN, mg_b2, 2, CC);
    mask5<<<dim3(HH, CC), 128>>>(m2, m1, mg_dw, mg_db, mf);

    // norms + gram + softmax
    norm_part<<<dim3(64, BB), 256>>>(q, k, npq, npk);
    norm_reduce<<<dim3(BB, 2), 256>>>(npq, npk, gnorm);
    gram_part<<<dim3(16, BB * HEADS), 256>>>(q, k, gp);
    softmax_k<<<4, 256>>>(gp, gnorm, rescale, attn);

    // out_tok = attn @ (v * mask_emb) -> bf16 hi/lo
    av_k<<<dim3(NN / 128, BB * HEADS), 128>>>(v, mf, attn, tokhi, toklo);

    // projection (tensor core) into d_out
    mmagemm<<<dim3(4, MROWS / 128), 256, MMASMEM>>>(tokhi, toklo, wph, wpl, out, out, out, bproj);

    // band_emb: dw3x3 -> GELU -> dw3x3, added into d_out
    dw3x3_k<<<dim3(HH, BB), 256>>>(v, be_w1, y1, 0);
    dw3x3_k<<<dim3(HH, BB), 256>>>(y1, be_w2, out, 1);
}

// round 9
// speedup vs baseline: 1.1189x; 1.0755x over previous
#include <cuda_runtime.h>
#include <cuda_bf16.h>
#include <stdint.h>
#include <math.h>

// Problem constants
#define BB 4
#define HH 128
#define WW 128
#define CC 256
#define HEADS 8
#define DD 32
#define NN (HH*WW)          // 16384 tokens per batch
#define MROWS (BB*NN)       // 65536 total rows
#define KDIM 256

// ---------------- scratch (__device__ globals; no allocations allowed) -------------
__device__ float g_q  [(size_t)MROWS*CC];
__device__ float g_k  [(size_t)MROWS*CC];
__device__ float g_v  [(size_t)MROWS*CC];
__device__ float g_y1 [(size_t)MROWS*CC];
__device__ float g_m1 [(size_t)CC*NN];
__device__ float g_m2 [(size_t)CC*NN];
__device__ float g_mf [(size_t)CC*NN];
__device__ float g_npq[64*BB*CC];
__device__ float g_npk[64*BB*CC];
__device__ float g_norm[2*BB*CC];
__device__ float g_gp [16*BB*HEADS*DD*DD];
__device__ float g_attn[BB*HEADS*DD*DD];

__device__ __nv_bfloat16 g_xhi [(size_t)MROWS*CC];
__device__ __nv_bfloat16 g_xlo [(size_t)MROWS*CC];
__device__ __nv_bfloat16 g_tokhi[(size_t)MROWS*CC];
__device__ __nv_bfloat16 g_toklo[(size_t)MROWS*CC];
__device__ __nv_bfloat16 g_wqkvh[768*256];
__device__ __nv_bfloat16 g_wqkvl[768*256];
__device__ __nv_bfloat16 g_wph  [256*256];
__device__ __nv_bfloat16 g_wpl  [256*256];
__device__ __nv_bfloat16 g_w1h  [256*256];
__device__ __nv_bfloat16 g_w1l  [256*256];
__device__ __nv_bfloat16 g_w2h  [256*256];
__device__ __nv_bfloat16 g_w2l  [256*256];
__device__ __nv_bfloat16 g_mTh  [(size_t)CC*NN];   // mask^T [N][C] hi
__device__ __nv_bfloat16 g_mTl  [(size_t)CC*NN];
__device__ __nv_bfloat16 g_m1th [(size_t)CC*NN];   // m1^T [N][C] hi
__device__ __nv_bfloat16 g_m1tl [(size_t)CC*NN];

// ---------------- fp32 -> bf16 hi/lo split (1024 elems per block) ------------------
__global__ __launch_bounds__(256) void split_bf16(
    const float* __restrict__ in, __nv_bfloat16* __restrict__ hi,
    __nv_bfloat16* __restrict__ lo)
{
    size_t i = ((size_t)blockIdx.x * 256 + threadIdx.x) * 4;
    float4 v = *(const float4*)(in + i);
    __nv_bfloat16 h0 = __float2bfloat16(v.x);
    __nv_bfloat16 h1 = __float2bfloat16(v.y);
    __nv_bfloat16 h2 = __float2bfloat16(v.z);
    __nv_bfloat16 h3 = __float2bfloat16(v.w);
    __nv_bfloat162 hp0; hp0.x = h0; hp0.y = h1;
    __nv_bfloat162 hp1; hp1.x = h2; hp1.y = h3;
    *(__nv_bfloat162*)(hi + i)     = hp0;
    *(__nv_bfloat162*)(hi + i + 2) = hp1;
    __nv_bfloat162 lp0, lp1;
    lp0.x = __float2bfloat16(v.x - __bfloat162float(h0));
    lp0.y = __float2bfloat16(v.y - __bfloat162float(h1));
    lp1.x = __float2bfloat16(v.z - __bfloat162float(h2));
    lp1.y = __float2bfloat16(v.w - __bfloat162float(h3));
    *(__nv_bfloat162*)(lo + i)     = lp0;
    *(__nv_bfloat162*)(lo + i + 2) = lp1;
}

// ---------------- pack weights transposed (Bt[n][k] = W[k][n]), split hi/lo --------
__global__ __launch_bounds__(256) void pack_wqkv(
    const float* __restrict__ wq, const float* __restrict__ wk,
    const float* __restrict__ wv,
    __nv_bfloat16* __restrict__ bh, __nv_bfloat16* __restrict__ bl)
{
    int n = blockIdx.x, k = threadIdx.x;
    int seg = n >> 8, lc = n & 255;
    const float* w = (seg == 0) ? wq : (seg == 1) ? wk : wv;
    float v = w[k * 256 + lc];
    __nv_bfloat16 h = __float2bfloat16(v);
    bh[n * 256 + k] = h;
    bl[n * 256 + k] = __float2bfloat16(v - __bfloat162float(h));
}

__global__ __launch_bounds__(256) void pack_w1(
    const float* __restrict__ w,
    __nv_bfloat16* __restrict__ bh, __nv_bfloat16* __restrict__ bl)
{
    int n = blockIdx.x, k = threadIdx.x;
    float v = w[k * 256 + n];
    __nv_bfloat16 h = __float2bfloat16(v);
    bh[n * 256 + k] = h;
    bl[n * 256 + k] = __float2bfloat16(v - __bfloat162float(h));
}

// ---------------- transpose + split: in fp32 [R][N] -> out hi/lo [N][R] ------------
// grid (N/32, R/32), block (32,8)
__global__ __launch_bounds__(256) void tr_split(
    const float* __restrict__ in, int R, int N,
    __nv_bfloat16* __restrict__ oh, __nv_bfloat16* __restrict__ ol)
{
    __shared__ float t[32][33];
    int c0 = blockIdx.x * 32, r0 = blockIdx.y * 32;
    int tx = threadIdx.x, ty = threadIdx.y;
    #pragma unroll
    for (int u = 0; u < 4; u++)
        t[ty + u * 8][tx] = in[(size_t)(r0 + ty + u * 8) * N + c0 + tx];
    __syncthreads();
    #pragma unroll
    for (int u = 0; u < 4; u++) {
        float v = t[tx][ty + u * 8];
        __nv_bfloat16 h = __float2bfloat16(v);
        size_t o = (size_t)(c0 + ty + u * 8) * R + r0 + tx;
        oh[o] = h;
        ol[o] = __float2bfloat16(v - __bfloat162float(h));
    }
}

// ---------------- bf16 split-3 tensor-core GEMM v2 ---------------------------------
// 4 warps, block tile 128x128, warp tile 64x64, ldmatrix frags, cp.async loads.
// A hi/lo [M][256] row-major, Bt hi/lo [N][256] n-major. K=256 fixed.
// mode 0: qkv/proj routing per 256-col segment (ldc=256). mode 1: single C0, ldc.
#define MMA_BF16(d, a, b0, b1) \
  asm volatile("mma.sync.aligned.m16n8k16.row.col.f32.bf16.bf16.f32 " \
      "{%0,%1,%2,%3}, {%4,%5,%6,%7}, {%8,%9}, {%0,%1,%2,%3};" \
      : "+f"(d[0]), "+f"(d[1]), "+f"(d[2]), "+f"(d[3]) \
      : "r"(a[0]), "r"(a[1]), "r"(a[2]), "r"(a[3]), "r"(b0), "r"(b1))

#define LDSM4(r, addr) \
  asm volatile("ldmatrix.sync.aligned.m8n8.x4.shared.b16 {%0,%1,%2,%3}, [%4];" \
      : "=r"(r[0]), "=r"(r[1]), "=r"(r[2]), "=r"(r[3]) : "r"(addr))

#define CPA16(dst, src) \
  asm volatile("cp.async.cg.shared.global [%0], [%1], 16;" :: "r"(dst), "l"(src))

#define APAD 40
#define CHEL (128*APAD)     // elems per chunk buffer (5120)

__global__ __launch_bounds__(128) void mmagemm2(
    const __nv_bfloat16* __restrict__ Ahi, const __nv_bfloat16* __restrict__ Alo,
    const __nv_bfloat16* __restrict__ Bth, const __nv_bfloat16* __restrict__ Btl,
    float* C0, float* C1, float* C2, const float* __restrict__ bias,
    int biasMode, int mode, int ldc)
{
    extern __shared__ __align__(16) __nv_bfloat16 sm[];
    // layout (elems): AH[2][CHEL], AL[2][CHEL], BH[2][CHEL], BL[2][CHEL]
    uint32_t smbase;
    asm("{ .reg .u64 t; cvta.to.shared.u64 t, %1; cvt.u32.u64 %0, t; }"
        : "=r"(smbase) : "l"(sm));

    const int tid = threadIdx.x;
    const int lane = tid & 31, warp = tid >> 5;
    const int g = lane >> 2, qq = lane & 3;
    const int wm = (warp >> 1) * 64, wn = (warp & 1) * 64;
    const int row0 = blockIdx.y * 128, colg = blockIdx.x * 128;

    const __nv_bfloat16* AgH = Ahi + (size_t)(row0 + tid) * KDIM;
    const __nv_bfloat16* AgL = Alo + (size_t)(row0 + tid) * KDIM;
    const __nv_bfloat16* BgH = Bth + (size_t)(colg + tid) * KDIM;
    const __nv_bfloat16* BgL = Btl + (size_t)(colg + tid) * KDIM;
    const uint32_t rowoff = tid * APAD * 2;   // byte offset of this thread's smem row

    // ldmatrix per-lane address components
    const int a_r = lane & 15;                 // A tile row within 16
    const int a_k = (lane >> 4) << 3;          // A tile k offset (0/8)
    const int b_r = (lane & 7) + ((lane >> 4) << 3);  // B row within 16
    const int b_k = lane & 8;                  // B k offset (0/8)

    float acc[4][8][4] = {};

    // preload chunk 0 into buf 0
    {
        #pragma unroll
        for (int s = 0; s < 4; s++) {
            uint32_t d = smbase + rowoff + s * 16;
            CPA16(d,                     AgH + s * 8);
            CPA16(d + 2*CHEL*2*1,        AgL + s * 8);
            CPA16(d + 2*CHEL*2*2,        BgH + s * 8);
            CPA16(d + 2*CHEL*2*3,        BgL + s * 8);
        }
        asm volatile("cp.async.commit_group;");
        asm volatile("cp.async.wait_group 0;");
    }
    __syncthreads();

    #pragma unroll 1
    for (int kt = 0; kt < 8; kt++) {
        const int buf = kt & 1;
        if (kt < 7) {
            const int kc = (kt + 1) * 32;
            const uint32_t bofs = (buf ^ 1) * CHEL * 2;
            #pragma unroll
            for (int s = 0; s < 4; s++) {
                uint32_t d = smbase + bofs + rowoff + s * 16;
                CPA16(d,              AgH + kc + s * 8);
                CPA16(d + 2*CHEL*2*1, AgL + kc + s * 8);
                CPA16(d + 2*CHEL*2*2, BgH + kc + s * 8);
                CPA16(d + 2*CHEL*2*3, BgL + kc + s * 8);
            }
            asm volatile("cp.async.commit_group;");
        }

        const uint32_t aH0 = smbase + buf * CHEL * 2;
        const uint32_t aL0 = aH0 + 2 * CHEL * 2;
        const uint32_t bH0 = aH0 + 4 * CHEL * 2;
        const uint32_t bL0 = aH0 + 6 * CHEL * 2;

        #pragma unroll
        for (int ki = 0; ki < 2; ki++) {
            uint32_t ah[4][4], al[4][4], bh[4][4], bl[4][4];
            const int kcol = ki * 16;
            #pragma unroll
            for (int mi = 0; mi < 4; mi++) {
                uint32_t off = (uint32_t)((wm + mi * 16 + a_r) * APAD + kcol + a_k) * 2;
                LDSM4(ah[mi], aH0 + off);
                LDSM4(al[mi], aL0 + off);
            }
            #pragma unroll
            for (int j = 0; j < 4; j++) {
                uint32_t off = (uint32_t)((wn + j * 16 + b_r) * APAD + kcol + b_k) * 2;
                LDSM4(bh[j], bH0 + off);
                LDSM4(bl[j], bL0 + off);
            }
            #pragma unroll
            for (int mi = 0; mi < 4; mi++)
                #pragma unroll
                for (int j = 0; j < 4; j++) {
                    MMA_BF16(acc[mi][2*j],   ah[mi], bh[j][0], bh[j][1]);
                    MMA_BF16(acc[mi][2*j],   ah[mi], bl[j][0], bl[j][1]);
                    MMA_BF16(acc[mi][2*j],   al[mi], bh[j][0], bh[j][1]);
                    MMA_BF16(acc[mi][2*j+1], ah[mi], bh[j][2], bh[j][3]);
                    MMA_BF16(acc[mi][2*j+1], ah[mi], bl[j][2], bl[j][3]);
                    MMA_BF16(acc[mi][2*j+1], al[mi], bh[j][2], bh[j][3]);
                }
        }

        asm volatile("cp.async.wait_group 0;");
        __syncthreads();
    }

    // epilogue
    float* outp;
    int cbase;
    if (mode == 0) {
        const int seg = colg >> 8;
        outp = (seg == 0) ? C0 : (seg == 1) ? C1 : C2;
        cbase = (colg & 255);
    } else {
        outp = C0;
        cbase = colg;
    }
    #pragma unroll
    for (int mi = 0; mi < 4; mi++) {
        const int r0 = row0 + wm + mi * 16 + g;
        float rb0 = 0.f, rb1 = 0.f;
        if (biasMode == 2) { rb0 = bias[r0]; rb1 = bias[r0 + 8]; }
        #pragma unroll
        for (int ni = 0; ni < 8; ni++) {
            const int col = cbase + wn + ni * 8 + 2 * qq;
            float b0 = rb0, b1 = rb0, b2 = rb1, b3 = rb1;
            if (biasMode == 1) {
                float bc0 = bias[col], bc1 = bias[col + 1];
                b0 = bc0; b1 = bc1; b2 = bc0; b3 = bc1;
            }
            float2 s0 = make_float2(acc[mi][ni][0] + b0, acc[mi][ni][1] + b1);
            float2 s1 = make_float2(acc[mi][ni][2] + b2, acc[mi][ni][3] + b3);
            *(float2*)(outp + (size_t)r0 * ldc + col)       = s0;
            *(float2*)(outp + (size_t)(r0 + 8) * ldc + col) = s1;
        }
    }
}

// ---------------- mask depthwise 5x5 + sigmoid + residual gate ---------------------
__global__ __launch_bounds__(128) void mask5(
    const float* __restrict__ m2, const float* __restrict__ m1,
    const float* __restrict__ dw, const float* __restrict__ db,
    float* __restrict__ mf)
{
    int x = threadIdx.x, y = blockIdx.x, c = blockIdx.y;
    __shared__ float ws[25];
    if (x < 25) ws[x] = dw[c * 25 + x];
    __syncthreads();
    float s = db[c];
    const float* mp = m2 + (size_t)c * NN;
    #pragma unroll
    for (int dy = -2; dy <= 2; dy++) {
        int yy = y + dy;
        if (yy < 0 || yy >= HH) continue;
        #pragma unroll
        for (int dx = -2; dx <= 2; dx++) {
            int xx = x + dx;
            if (xx < 0 || xx >= WW) continue;
            s = fmaf(ws[(dy + 2) * 5 + (dx + 2)], mp[yy * WW + xx], s);
        }
    }
    float sig = 1.f / (1.f + expf(-s));
    int p = y * WW + x;
    float a = m1[(size_t)c * NN + p];
    mf[(size_t)c * NN + p] = fmaf(a, sig, a);
}

// ---------------- column L2-norm partials ------------------------------------------
__global__ __launch_bounds__(256) void norm_part(
    const float* __restrict__ q, const float* __restrict__ k,
    float* __restrict__ npq, float* __restrict__ npk)
{
    int chunk = blockIdx.x, b = blockIdx.y, c = threadIdx.x;
    size_t base = ((size_t)b * NN + chunk * 256) * CC + c;
    float sq = 0.f, sk = 0.f;
    #pragma unroll 8
    for (int t = 0; t < 256; t++) {
        float v1 = q[base + (size_t)t * CC]; sq = fmaf(v1, v1, sq);
        float v2 = k[base + (size_t)t * CC]; sk = fmaf(v2, v2, sk);
    }
    int o = (chunk * BB + b) * CC + c;
    npq[o] = sq; npk[o] = sk;
}

__global__ __launch_bounds__(256) void norm_reduce(
    const float* __restrict__ npq, const float* __restrict__ npk,
    float* __restrict__ gnorm)
{
    int b = blockIdx.x, sel = blockIdx.y, c = threadIdx.x;
    const float* np = sel ? npk : npq;
    float s = 0.f;
    #pragma unroll 8
    for (int ch = 0; ch < 64; ch++) s += np[(ch * BB + b) * CC + c];
    float n = sqrtf(s);
    if (n < 1e-12f) n = 1e-12f;
    gnorm[sel * (BB * CC) + b * CC + c] = n;
}

// ---------------- gram partials (2x2 register microtile) ---------------------------
__global__ __launch_bounds__(256) void gram_part(
    const float* __restrict__ q, const float* __restrict__ k,
    float* __restrict__ gp)
{
    __shared__ float Ks[64][33];
    __shared__ float Qs[64][33];
    int sp = blockIdx.x, bh = blockIdx.y;
    int b = bh >> 3, h = bh & 7;
    int tid = threadIdx.x;
    int i0 = tid >> 4, j0 = tid & 15;
    float a00 = 0.f, a01 = 0.f, a10 = 0.f, a11 = 0.f;

    for (int t = 0; t < 16; t++) {
        int n0 = sp * 1024 + t * 64;
        #pragma unroll
        for (int i = 0; i < 8; i++) {
            int idx = tid + i * 256;
            int tok = idx >> 5, j = idx & 31;
            size_t gg = ((size_t)b * NN + n0 + tok) * CC + h * DD + j;
            Ks[tok][j] = k[gg];
            Qs[tok][j] = q[gg];
        }
        __syncthreads();
        #pragma unroll
        for (int kk = 0; kk < 64; kk++) {
            float k0 = Ks[kk][i0], k1 = Ks[kk][i0 + 16];
            float q0 = Qs[kk][j0], q1 = Qs[kk][j0 + 16];
            a00 = fmaf(k0, q0, a00);
            a01 = fmaf(k0, q1, a01);
            a10 = fmaf(k1, q0, a10);
            a11 = fmaf(k1, q1, a11);
        }
        __syncthreads();
    }
    size_t base = ((size_t)(sp * 32 + bh)) * 1024;
    gp[base + i0 * 32 + j0]             = a00;
    gp[base + i0 * 32 + j0 + 16]        = a01;
    gp[base + (i0 + 16) * 32 + j0]      = a10;
    gp[base + (i0 + 16) * 32 + j0 + 16] = a11;
}

// ---------------- softmax over gram ------------------------------------------------
__global__ __launch_bounds__(256) void softmax_k(
    const float* __restrict__ gp, const float* __restrict__ gnorm,
    const float* __restrict__ rescale, float* __restrict__ attn)
{
    int gid = blockIdx.x * 256 + threadIdx.x;
    int b = gid >> 8, rem = gid & 255;
    int h = rem >> 5, i = rem & 31;
    int bh = b * HEADS + h;
    float kn = gnorm[BB * CC + b * CC + h * DD + i];
    float rs = rescale[h];
    float vals[32];
    float mx = -1e30f;
    #pragma unroll
    for (int j = 0; j < 32; j++) {
        float gsum = 0.f;
        #pragma unroll
        for (int s = 0; s < 16; s++) gsum += gp[((size_t)(s * 32 + bh)) * 1024 + i * 32 + j];
        float qn = gnorm[b * CC + h * DD + j];
        float val = gsum / (kn * qn) * rs;
        vals[j] = val;
        mx = fmaxf(mx, val);
    }
    float sum = 0.f;
    #pragma unroll
    for (int j = 0; j < 32; j++) { vals[j] = expf(vals[j] - mx); sum += vals[j]; }
    float inv = 1.f / sum;
    #pragma unroll
    for (int j = 0; j < 32; j++)
        attn[(size_t)bh * 1024 + i * 32 + j] = vals[j] * inv;
}

// ---------------- out_tok = attn @ (v*mask) -> bf16 hi/lo --------------------------
__global__ __launch_bounds__(128) void av_k(
    const float* __restrict__ v, const float* __restrict__ mf,
    const float* __restrict__ attn,
    __nv_bfloat16* __restrict__ tokhi, __nv_bfloat16* __restrict__ toklo)
{
    __shared__ __align__(16) float At[1024];
    __shared__ float Vs[128][33];
    __shared__ float Ms[32][128];
    int bh = blockIdx.y;
    int b = bh >> 3, h = bh & 7;
    int n0 = blockIdx.x * 128;
    int tid = threadIdx.x;
    #pragma unroll
    for (int i = 0; i < 8; i++) At[tid + i * 128] = attn[(size_t)bh * 1024 + tid + i * 128];
    #pragma unroll
    for (int i = 0; i < 32; i++) {
        int idx = tid + i * 128;
        int tk = idx >> 5, j = idx & 31;
        Vs[tk][j] = v[((size_t)b * NN + n0 + tk) * CC + h * DD + j];
        int jm = idx >> 7, tm = idx & 127;
        Ms[jm][tm] = mf[(size_t)(h * DD + jm) * NN + n0 + tm];
    }
    __syncthreads();
    int t = tid;
    float vm[32];
    #pragma unroll
    for (int j = 0; j < 32; j++) vm[j] = Vs[t][j] * Ms[j][t];
    size_t obase = ((size_t)b * NN + n0 + t) * CC + h * DD;
    const float4* At4 = (const float4*)At;
    #pragma unroll
    for (int i = 0; i < 32; i++) {
        float o = 0.f;
        #pragma unroll
        for (int jv = 0; jv < 8; jv++) {
            float4 w = At4[i * 8 + jv];
            o = fmaf(w.x, vm[jv * 4 + 0], o);
            o = fmaf(w.y, vm[jv * 4 + 1], o);
            o = fmaf(w.z, vm[jv * 4 + 2], o);
            o = fmaf(w.w, vm[jv * 4 + 3], o);
        }
        __nv_bfloat16 hi = __float2bfloat16(o);
        tokhi[obase + i] = hi;
        toklo[obase + i] = __float2bfloat16(o - __bfloat162float(hi));
    }
}

// ---------------- depthwise 3x3 (pad=1), rolling register window -------------------
__global__ __launch_bounds__(256) void dw3x3_k(
    const float* __restrict__ in, const float* __restrict__ w9,
    float* __restrict__ out, int mode)
{
    __shared__ float ws[9 * CC];
    int c = threadIdx.x;
    int y = blockIdx.x, b = blockIdx.y;
    #pragma unroll
    for (int i = 0; i < 9; i++) ws[c + i * CC] = w9[c + i * CC];
    __syncthreads();
    float wv[9];
    #pragma unroll
    for (int t = 0; t < 9; t++) wv[t] = ws[c * 9 + t];
    const size_t base = (size_t)b * NN * CC + c;
    float a[3][3];
    #pragma unroll
    for (int r = 0; r < 3; r++) {
        int yy = y - 1 + r;
        bool yok = (yy >= 0 && yy < HH);
        a[r][0] = 0.f;
        a[r][1] = yok ? in[base + (size_t)(yy * WW + 0) * CC] : 0.f;
        a[r][2] = yok ? in[base + (size_t)(yy * WW + 1) * CC] : 0.f;
    }
    for (int x = 0; x < WW; x++) {
        float acc = 0.f;
        #pragma unroll
        for (int r = 0; r < 3; r++)
            #pragma unroll
            for (int k2 = 0; k2 < 3; k2++)
                acc = fmaf(wv[r * 3 + k2], a[r][k2], acc);
        size_t o = base + (size_t)(y * WW + x) * CC;
        if (mode == 0) {
            acc = 0.5f * acc * (1.f + erff(acc * 0.70710678118654752f));
            out[o] = acc;
        } else {
            out[o] += acc;
        }
        int xn = x + 2;
        bool xok = (xn < WW);
        #pragma unroll
        for (int r = 0; r < 3; r++) {
            int yy = y - 1 + r;
            bool ok = xok && (yy >= 0 && yy < HH);
            a[r][0] = a[r][1];
            a[r][1] = a[r][2];
            a[r][2] = ok ? in[base + (size_t)(yy * WW + xn) * CC] : 0.f;
        }
    }
}

// ================================= launch ==========================================
extern "C" void kernel_launch(void* const* d_in, const int* in_sizes, int n_in,
                              void* d_out, int out_size)
{
    const float* x      = (const float*)d_in[0];
    const float* mask   = (const float*)d_in[1];
    const float* wq     = (const float*)d_in[2];
    const float* wk     = (const float*)d_in[3];
    const float* wv     = (const float*)d_in[4];
    const float* rescale= (const float*)d_in[5];
    const float* wproj  = (const float*)d_in[6];
    const float* bproj  = (const float*)d_in[7];
    const float* mg_w1  = (const float*)d_in[8];
    const float* mg_b1  = (const float*)d_in[9];
    const float* mg_w2  = (const float*)d_in[10];
    const float* mg_b2  = (const float*)d_in[11];
    const float* mg_dw  = (const float*)d_in[12];
    const float* mg_db  = (const float*)d_in[13];
    const float* be_w1  = (const float*)d_in[14];
    const float* be_w2  = (const float*)d_in[15];
    float* out = (float*)d_out;

    float *q, *k, *v, *y1, *m1, *m2, *mf, *npq, *npk, *gnorm, *gp, *attn;
    __nv_bfloat16 *xhi, *xlo, *tokhi, *toklo, *wqkvh, *wqkvl, *wph, *wpl;
    __nv_bfloat16 *w1h, *w1l, *w2h, *w2l, *mTh, *mTl, *m1th, *m1tl;
    cudaGetSymbolAddress((void**)&q,    g_q);
    cudaGetSymbolAddress((void**)&k,    g_k);
    cudaGetSymbolAddress((void**)&v,    g_v);
    cudaGetSymbolAddress((void**)&y1,   g_y1);
    cudaGetSymbolAddress((void**)&m1,   g_m1);
    cudaGetSymbolAddress((void**)&m2,   g_m2);
    cudaGetSymbolAddress((void**)&mf,   g_mf);
    cudaGetSymbolAddress((void**)&npq,  g_npq);
    cudaGetSymbolAddress((void**)&npk,  g_npk);
    cudaGetSymbolAddress((void**)&gnorm,g_norm);
    cudaGetSymbolAddress((void**)&gp,   g_gp);
    cudaGetSymbolAddress((void**)&attn, g_attn);
    cudaGetSymbolAddress((void**)&xhi,  g_xhi);
    cudaGetSymbolAddress((void**)&xlo,  g_xlo);
    cudaGetSymbolAddress((void**)&tokhi,g_tokhi);
    cudaGetSymbolAddress((void**)&toklo,g_toklo);
    cudaGetSymbolAddress((void**)&wqkvh,g_wqkvh);
    cudaGetSymbolAddress((void**)&wqkvl,g_wqkvl);
    cudaGetSymbolAddress((void**)&wph,  g_wph);
    cudaGetSymbolAddress((void**)&wpl,  g_wpl);
    cudaGetSymbolAddress((void**)&w1h,  g_w1h);
    cudaGetSymbolAddress((void**)&w1l,  g_w1l);
    cudaGetSymbolAddress((void**)&w2h,  g_w2h);
    cudaGetSymbolAddress((void**)&w2l,  g_w2l);
    cudaGetSymbolAddress((void**)&mTh,  g_mTh);
    cudaGetSymbolAddress((void**)&mTl,  g_mTl);
    cudaGetSymbolAddress((void**)&m1th, g_m1th);
    cudaGetSymbolAddress((void**)&m1tl, g_m1tl);

    const int MMASMEM = 8 * CHEL * 2;   // 81920 bytes
    cudaFuncSetAttribute(mmagemm2, cudaFuncAttributeMaxDynamicSharedMemorySize, MMASMEM);

    // prep: splits + packs + transposes
    split_bf16<<<(MROWS * CC) / 1024, 256>>>(x, xhi, xlo);
    split_bf16<<<(CC * CC) / 1024, 256>>>(mg_w1, w1h, w1l);
    split_bf16<<<(CC * CC) / 1024, 256>>>(mg_w2, w2h, w2l);
    pack_wqkv<<<768, 256>>>(wq, wk, wv, wqkvh, wqkvl);
    pack_w1<<<256, 256>>>(wproj, wph, wpl);
    tr_split<<<dim3(NN / 32, CC / 32), dim3(32, 8)>>>(mask, CC, NN, mTh, mTl);

    // fused qkv: [65536,256] @ [256,768]
    mmagemm2<<<dim3(6, MROWS / 128), 128, MMASMEM>>>(
        xhi, xlo, wqkvh, wqkvl, q, k, v, nullptr, 0, 0, 256);

    // mask-guided path via tensor cores: m1 = W1@mask + b1; m2 = W2@m1 + b2
    mmagemm2<<<dim3(NN / 128, CC / 128), 128, MMASMEM>>>(
        w1h, w1l, mTh, mTl, m1, nullptr, nullptr, mg_b1, 2, 1, NN);
    tr_split<<<dim3(NN / 32, CC / 32), dim3(32, 8)>>>(m1, CC, NN, m1th, m1tl);
    mmagemm2<<<dim3(NN / 128, CC / 128), 128, MMASMEM>>>(
        w2h, w2l, m1th, m1tl, m2, nullptr, nullptr, mg_b2, 2, 1, NN);
    mask5<<<dim3(HH, CC), 128>>>(m2, m1, mg_dw, mg_db, mf);

    // norms + gram + softmax
    norm_part<<<dim3(64, BB), 256>>>(q, k, npq, npk);
    norm_reduce<<<dim3(BB, 2), 256>>>(npq, npk, gnorm);
    gram_part<<<dim3(16, BB * HEADS), 256>>>(q, k, gp);
    softmax_k<<<4, 256>>>(gp, gnorm, rescale, attn);

    // out_tok = attn @ (v * mask_emb) -> bf16 hi/lo
    av_k<<<dim3(NN / 128, BB * HEADS), 128>>>(v, mf, attn, tokhi, toklo);

    // projection into d_out
    mmagemm2<<<dim3(2, MROWS / 128), 128, MMASMEM>>>(
        tokhi, toklo, wph, wpl, out, out, out, bproj, 1, 0, 256);

    // band_emb: dw3x3 -> GELU -> dw3x3, added into d_out
    dw3x3_k<<<dim3(HH, BB), 256>>>(v, be_w1, y1, 0);
    dw3x3_k<<<dim3(HH, BB), 256>>>(y1, be_w2, out, 1);
}

// round 16
// speedup vs baseline: 1.1678x; 1.0437x over previous
#include <cuda_runtime.h>
#include <cuda_bf16.h>
#include <stdint.h>
#include <math.h>

// Problem constants
#define BB 4
#define HH 128
#define WW 128
#define CC 256
#define HEADS 8
#define DD 32
#define NN (HH*WW)          // 16384 tokens per batch
#define MROWS (BB*NN)       // 65536 total rows
#define KDIM 256

// ---------------- scratch (__device__ globals; no allocations allowed) -------------
__device__ float g_q  [(size_t)MROWS*CC];
__device__ float g_k  [(size_t)MROWS*CC];
__device__ float g_v  [(size_t)MROWS*CC];
__device__ float g_y1 [(size_t)MROWS*CC];
__device__ float g_m1 [(size_t)CC*NN];
__device__ float g_m2 [(size_t)CC*NN];
__device__ float g_mf [(size_t)CC*NN];
__device__ float g_npq[64*BB*CC];
__device__ float g_npk[64*BB*CC];
__device__ float g_norm[2*BB*CC];
__device__ float g_gp [16*BB*HEADS*DD*DD];
__device__ float g_attn[BB*HEADS*DD*DD];

__device__ __nv_bfloat16 g_xhi [(size_t)MROWS*CC];
__device__ __nv_bfloat16 g_xlo [(size_t)MROWS*CC];
__device__ __nv_bfloat16 g_tokhi[(size_t)MROWS*CC];
__device__ __nv_bfloat16 g_toklo[(size_t)MROWS*CC];
__device__ __nv_bfloat16 g_wqkvh[768*256];
__device__ __nv_bfloat16 g_wqkvl[768*256];
__device__ __nv_bfloat16 g_wph  [256*256];
__device__ __nv_bfloat16 g_wpl  [256*256];
__device__ __nv_bfloat16 g_w1h  [256*256];
__device__ __nv_bfloat16 g_w1l  [256*256];
__device__ __nv_bfloat16 g_w2h  [256*256];
__device__ __nv_bfloat16 g_w2l  [256*256];
__device__ __nv_bfloat16 g_mTh  [(size_t)CC*NN];   // mask^T [N][C] hi
__device__ __nv_bfloat16 g_mTl  [(size_t)CC*NN];
__device__ __nv_bfloat16 g_m1th [(size_t)CC*NN];   // m1^T [N][C] hi
__device__ __nv_bfloat16 g_m1tl [(size_t)CC*NN];

// ---------------- fp32 -> bf16 hi/lo split (1024 elems per block) ------------------
__global__ __launch_bounds__(256) void split_bf16(
    const float* __restrict__ in, __nv_bfloat16* __restrict__ hi,
    __nv_bfloat16* __restrict__ lo)
{
    size_t i = ((size_t)blockIdx.x * 256 + threadIdx.x) * 4;
    float4 v = *(const float4*)(in + i);
    __nv_bfloat16 h0 = __float2bfloat16(v.x);
    __nv_bfloat16 h1 = __float2bfloat16(v.y);
    __nv_bfloat16 h2 = __float2bfloat16(v.z);
    __nv_bfloat16 h3 = __float2bfloat16(v.w);
    __nv_bfloat162 hp0; hp0.x = h0; hp0.y = h1;
    __nv_bfloat162 hp1; hp1.x = h2; hp1.y = h3;
    *(__nv_bfloat162*)(hi + i)     = hp0;
    *(__nv_bfloat162*)(hi + i + 2) = hp1;
    __nv_bfloat162 lp0, lp1;
    lp0.x = __float2bfloat16(v.x - __bfloat162float(h0));
    lp0.y = __float2bfloat16(v.y - __bfloat162float(h1));
    lp1.x = __float2bfloat16(v.z - __bfloat162float(h2));
    lp1.y = __float2bfloat16(v.w - __bfloat162float(h3));
    *(__nv_bfloat162*)(lo + i)     = lp0;
    *(__nv_bfloat162*)(lo + i + 2) = lp1;
}

// ---------------- pack weights transposed (Bt[n][k] = W[k][n]), split hi/lo --------
__global__ __launch_bounds__(256) void pack_wqkv(
    const float* __restrict__ wq, const float* __restrict__ wk,
    const float* __restrict__ wv,
    __nv_bfloat16* __restrict__ bh, __nv_bfloat16* __restrict__ bl)
{
    int n = blockIdx.x, k = threadIdx.x;
    int seg = n >> 8, lc = n & 255;
    const float* w = (seg == 0) ? wq : (seg == 1) ? wk : wv;
    float v = w[k * 256 + lc];
    __nv_bfloat16 h = __float2bfloat16(v);
    bh[n * 256 + k] = h;
    bl[n * 256 + k] = __float2bfloat16(v - __bfloat162float(h));
}

__global__ __launch_bounds__(256) void pack_w1(
    const float* __restrict__ w,
    __nv_bfloat16* __restrict__ bh, __nv_bfloat16* __restrict__ bl)
{
    int n = blockIdx.x, k = threadIdx.x;
    float v = w[k * 256 + n];
    __nv_bfloat16 h = __float2bfloat16(v);
    bh[n * 256 + k] = h;
    bl[n * 256 + k] = __float2bfloat16(v - __bfloat162float(h));
}

// ---------------- transpose + split: in fp32 [R][N] -> out hi/lo [N][R] ------------
// grid (N/32, R/32), block (32,8)
__global__ __launch_bounds__(256) void tr_split(
    const float* __restrict__ in, int R, int N,
    __nv_bfloat16* __restrict__ oh, __nv_bfloat16* __restrict__ ol)
{
    __shared__ float t[32][33];
    int c0 = blockIdx.x * 32, r0 = blockIdx.y * 32;
    int tx = threadIdx.x, ty = threadIdx.y;
    #pragma unroll
    for (int u = 0; u < 4; u++)
        t[ty + u * 8][tx] = in[(size_t)(r0 + ty + u * 8) * N + c0 + tx];
    __syncthreads();
    #pragma unroll
    for (int u = 0; u < 4; u++) {
        float v = t[tx][ty + u * 8];
        __nv_bfloat16 h = __float2bfloat16(v);
        size_t o = (size_t)(c0 + ty + u * 8) * R + r0 + tx;
        oh[o] = h;
        ol[o] = __float2bfloat16(v - __bfloat162float(h));
    }
}

// ---------------- bf16 split-3 tensor-core GEMM v3 ---------------------------------
// 16 warps (512 thr), block tile 128x128, warp tile 32x32, ldmatrix, cp.async.
// A hi/lo [M][256] row-major, Bt hi/lo [N][256] n-major. K=256 fixed.
// mode 0: qkv/proj routing per 256-col segment (ldc=256). mode 1: single C0, ldc.
#define MMA_BF16(d, a, b0, b1) \
  asm volatile("mma.sync.aligned.m16n8k16.row.col.f32.bf16.bf16.f32 " \
      "{%0,%1,%2,%3}, {%4,%5,%6,%7}, {%8,%9}, {%0,%1,%2,%3};" \
      : "+f"(d[0]), "+f"(d[1]), "+f"(d[2]), "+f"(d[3]) \
      : "r"(a[0]), "r"(a[1]), "r"(a[2]), "r"(a[3]), "r"(b0), "r"(b1))

#define LDSM4(r, addr) \
  asm volatile("ldmatrix.sync.aligned.m8n8.x4.shared.b16 {%0,%1,%2,%3}, [%4];" \
      : "=r"(r[0]), "=r"(r[1]), "=r"(r[2]), "=r"(r[3]) : "r"(addr))

#define CPA16(dst, src) \
  asm volatile("cp.async.cg.shared.global [%0], [%1], 16;" :: "r"(dst), "l"(src))

#define APAD 40
#define CHEL (128*APAD)     // elems per chunk buffer (5120)

__global__ __launch_bounds__(512) void mmagemm2(
    const __nv_bfloat16* __restrict__ Ahi, const __nv_bfloat16* __restrict__ Alo,
    const __nv_bfloat16* __restrict__ Bth, const __nv_bfloat16* __restrict__ Btl,
    float* C0, float* C1, float* C2, const float* __restrict__ bias,
    int biasMode, int mode, int ldc)
{
    extern __shared__ __align__(16) __nv_bfloat16 sm[];
    // layout (elems): AH[2][CHEL], AL[2][CHEL], BH[2][CHEL], BL[2][CHEL]
    uint32_t smbase;
    asm("{ .reg .u64 t; cvta.to.shared.u64 t, %1; cvt.u32.u64 %0, t; }"
        : "=r"(smbase) : "l"(sm));

    const int tid = threadIdx.x;
    const int lane = tid & 31, warp = tid >> 5;
    const int g = lane >> 2, qq = lane & 3;
    const int wm = (warp >> 2) * 32, wn = (warp & 3) * 32;
    const int row0 = blockIdx.y * 128, colg = blockIdx.x * 128;

    // loader mapping: 512 threads, 1x 16B chunk per buffer per stage
    const int lr = tid >> 2, ls = tid & 3;
    const __nv_bfloat16* AgH = Ahi + (size_t)(row0 + lr) * KDIM + ls * 8;
    const __nv_bfloat16* AgL = Alo + (size_t)(row0 + lr) * KDIM + ls * 8;
    const __nv_bfloat16* BgH = Bth + (size_t)(colg + lr) * KDIM + ls * 8;
    const __nv_bfloat16* BgL = Btl + (size_t)(colg + lr) * KDIM + ls * 8;
    const uint32_t stoff = (uint32_t)(lr * APAD + ls * 8) * 2;   // byte offset in buffer

    // ldmatrix per-lane address components
    const int a_r = lane & 15;                 // A tile row within 16
    const int a_k = (lane >> 4) << 3;          // A tile k offset (0/8)
    const int b_r = (lane & 7) + ((lane >> 4) << 3);  // B row within 16
    const int b_k = lane & 8;                  // B k offset (0/8)

    float acc[2][4][4] = {};

    // preload chunk 0 into buf 0
    {
        uint32_t d = smbase + stoff;
        CPA16(d,              AgH);
        CPA16(d + 2*CHEL*2*1, AgL);
        CPA16(d + 2*CHEL*2*2, BgH);
        CPA16(d + 2*CHEL*2*3, BgL);
        asm volatile("cp.async.commit_group;");
        asm volatile("cp.async.wait_group 0;");
    }
    __syncthreads();

    #pragma unroll 1
    for (int kt = 0; kt < 8; kt++) {
        const int buf = kt & 1;
        if (kt < 7) {
            const int kc = (kt + 1) * 32;
            const uint32_t bofs = (buf ^ 1) * CHEL * 2;
            uint32_t d = smbase + bofs + stoff;
            CPA16(d,              AgH + kc);
            CPA16(d + 2*CHEL*2*1, AgL + kc);
            CPA16(d + 2*CHEL*2*2, BgH + kc);
            CPA16(d + 2*CHEL*2*3, BgL + kc);
            asm volatile("cp.async.commit_group;");
        }

        const uint32_t aH0 = smbase + buf * CHEL * 2;
        const uint32_t aL0 = aH0 + 2 * CHEL * 2;
        const uint32_t bH0 = aH0 + 4 * CHEL * 2;
        const uint32_t bL0 = aH0 + 6 * CHEL * 2;

        #pragma unroll
        for (int ki = 0; ki < 2; ki++) {
            uint32_t ah[2][4], al[2][4], bh[2][4], bl[2][4];
            const int kcol = ki * 16;
            #pragma unroll
            for (int mi = 0; mi < 2; mi++) {
                uint32_t off = (uint32_t)((wm + mi * 16 + a_r) * APAD + kcol + a_k) * 2;
                LDSM4(ah[mi], aH0 + off);
                LDSM4(al[mi], aL0 + off);
            }
            #pragma unroll
            for (int j = 0; j < 2; j++) {
                uint32_t off = (uint32_t)((wn + j * 16 + b_r) * APAD + kcol + b_k) * 2;
                LDSM4(bh[j], bH0 + off);
                LDSM4(bl[j], bL0 + off);
            }
            #pragma unroll
            for (int mi = 0; mi < 2; mi++)
                #pragma unroll
                for (int j = 0; j < 2; j++) {
                    MMA_BF16(acc[mi][2*j],   ah[mi], bh[j][0], bh[j][1]);
                    MMA_BF16(acc[mi][2*j],   ah[mi], bl[j][0], bl[j][1]);
                    MMA_BF16(acc[mi][2*j],   al[mi], bh[j][0], bh[j][1]);
                    MMA_BF16(acc[mi][2*j+1], ah[mi], bh[j][2], bh[j][3]);
                    MMA_BF16(acc[mi][2*j+1], ah[mi], bl[j][2], bl[j][3]);
                    MMA_BF16(acc[mi][2*j+1], al[mi], bh[j][2], bh[j][3]);
                }
        }

        asm volatile("cp.async.wait_group 0;");
        __syncthreads();
    }

    // epilogue
    float* outp;
    int cbase;
    if (mode == 0) {
        const int seg = colg >> 8;
        outp = (seg == 0) ? C0 : (seg == 1) ? C1 : C2;
        cbase = (colg & 255);
    } else {
        outp = C0;
        cbase = colg;
    }
    #pragma unroll
    for (int mi = 0; mi < 2; mi++) {
        const int r0 = row0 + wm + mi * 16 + g;
        float rb0 = 0.f, rb1 = 0.f;
        if (biasMode == 2) { rb0 = bias[r0]; rb1 = bias[r0 + 8]; }
        #pragma unroll
        for (int ni = 0; ni < 4; ni++) {
            const int col = cbase + wn + ni * 8 + 2 * qq;
            float b0 = rb0, b1 = rb0, b2 = rb1, b3 = rb1;
            if (biasMode == 1) {
                float bc0 = bias[col], bc1 = bias[col + 1];
                b0 = bc0; b1 = bc1; b2 = bc0; b3 = bc1;
            }
            float2 s0 = make_float2(acc[mi][ni][0] + b0, acc[mi][ni][1] + b1);
            float2 s1 = make_float2(acc[mi][ni][2] + b2, acc[mi][ni][3] + b3);
            *(float2*)(outp + (size_t)r0 * ldc + col)       = s0;
            *(float2*)(outp + (size_t)(r0 + 8) * ldc + col) = s1;
        }
    }
}

// ---------------- mask depthwise 5x5 + sigmoid + residual gate ---------------------
__global__ __launch_bounds__(128) void mask5(
    const float* __restrict__ m2, const float* __restrict__ m1,
    const float* __restrict__ dw, const float* __restrict__ db,
    float* __restrict__ mf)
{
    int x = threadIdx.x, y = blockIdx.x, c = blockIdx.y;
    __shared__ float ws[25];
    if (x < 25) ws[x] = dw[c * 25 + x];
    __syncthreads();
    float s = db[c];
    const float* mp = m2 + (size_t)c * NN;
    #pragma unroll
    for (int dy = -2; dy <= 2; dy++) {
        int yy = y + dy;
        if (yy < 0 || yy >= HH) continue;
        #pragma unroll
        for (int dx = -2; dx <= 2; dx++) {
            int xx = x + dx;
            if (xx < 0 || xx >= WW) continue;
            s = fmaf(ws[(dy + 2) * 5 + (dx + 2)], mp[yy * WW + xx], s);
        }
    }
    float sig = 1.f / (1.f + expf(-s));
    int p = y * WW + x;
    float a = m1[(size_t)c * NN + p];
    mf[(size_t)c * NN + p] = fmaf(a, sig, a);
}

// ---------------- column L2-norm partials ------------------------------------------
__global__ __launch_bounds__(256) void norm_part(
    const float* __restrict__ q, const float* __restrict__ k,
    float* __restrict__ npq, float* __restrict__ npk)
{
    int chunk = blockIdx.x, b = blockIdx.y, c = threadIdx.x;
    size_t base = ((size_t)b * NN + chunk * 256) * CC + c;
    float sq = 0.f, sk = 0.f;
    #pragma unroll 8
    for (int t = 0; t < 256; t++) {
        float v1 = q[base + (size_t)t * CC]; sq = fmaf(v1, v1, sq);
        float v2 = k[base + (size_t)t * CC]; sk = fmaf(v2, v2, sk);
    }
    int o = (chunk * BB + b) * CC + c;
    npq[o] = sq; npk[o] = sk;
}

__global__ __launch_bounds__(256) void norm_reduce(
    const float* __restrict__ npq, const float* __restrict__ npk,
    float* __restrict__ gnorm)
{
    int b = blockIdx.x, sel = blockIdx.y, c = threadIdx.x;
    const float* np = sel ? npk : npq;
    float s = 0.f;
    #pragma unroll 8
    for (int ch = 0; ch < 64; ch++) s += np[(ch * BB + b) * CC + c];
    float n = sqrtf(s);
    if (n < 1e-12f) n = 1e-12f;
    gnorm[sel * (BB * CC) + b * CC + c] = n;
}

// ---------------- gram partials (2x2 register microtile) ---------------------------
__global__ __launch_bounds__(256) void gram_part(
    const float* __restrict__ q, const float* __restrict__ k,
    float* __restrict__ gp)
{
    __shared__ float Ks[64][33];
    __shared__ float Qs[64][33];
    int sp = blockIdx.x, bh = blockIdx.y;
    int b = bh >> 3, h = bh & 7;
    int tid = threadIdx.x;
    int i0 = tid >> 4, j0 = tid & 15;
    float a00 = 0.f, a01 = 0.f, a10 = 0.f, a11 = 0.f;

    for (int t = 0; t < 16; t++) {
        int n0 = sp * 1024 + t * 64;
        #pragma unroll
        for (int i = 0; i < 8; i++) {
            int idx = tid + i * 256;
            int tok = idx >> 5, j = idx & 31;
            size_t gg = ((size_t)b * NN + n0 + tok) * CC + h * DD + j;
            Ks[tok][j] = k[gg];
            Qs[tok][j] = q[gg];
        }
        __syncthreads();
        #pragma unroll
        for (int kk = 0; kk < 64; kk++) {
            float k0 = Ks[kk][i0], k1 = Ks[kk][i0 + 16];
            float q0 = Qs[kk][j0], q1 = Qs[kk][j0 + 16];
            a00 = fmaf(k0, q0, a00);
            a01 = fmaf(k0, q1, a01);
            a10 = fmaf(k1, q0, a10);
            a11 = fmaf(k1, q1, a11);
        }
        __syncthreads();
    }
    size_t base = ((size_t)(sp * 32 + bh)) * 1024;
    gp[base + i0 * 32 + j0]             = a00;
    gp[base + i0 * 32 + j0 + 16]        = a01;
    gp[base + (i0 + 16) * 32 + j0]      = a10;
    gp[base + (i0 + 16) * 32 + j0 + 16] = a11;
}

// ---------------- softmax over gram ------------------------------------------------
__global__ __launch_bounds__(256) void softmax_k(
    const float* __restrict__ gp, const float* __restrict__ gnorm,
    const float* __restrict__ rescale, float* __restrict__ attn)
{
    int gid = blockIdx.x * 256 + threadIdx.x;
    int b = gid >> 8, rem = gid & 255;
    int h = rem >> 5, i = rem & 31;
    int bh = b * HEADS + h;
    float kn = gnorm[BB * CC + b * CC + h * DD + i];
    float rs = rescale[h];
    float vals[32];
    float mx = -1e30f;
    #pragma unroll
    for (int j = 0; j < 32; j++) {
        float gsum = 0.f;
        #pragma unroll
        for (int s = 0; s < 16; s++) gsum += gp[((size_t)(s * 32 + bh)) * 1024 + i * 32 + j];
        float qn = gnorm[b * CC + h * DD + j];
        float val = gsum / (kn * qn) * rs;
        vals[j] = val;
        mx = fmaxf(mx, val);
    }
    float sum = 0.f;
    #pragma unroll
    for (int j = 0; j < 32; j++) { vals[j] = expf(vals[j] - mx); sum += vals[j]; }
    float inv = 1.f / sum;
    #pragma unroll
    for (int j = 0; j < 32; j++)
        attn[(size_t)bh * 1024 + i * 32 + j] = vals[j] * inv;
}

// ---------------- out_tok = attn @ (v*mask) -> bf16 hi/lo --------------------------
__global__ __launch_bounds__(128) void av_k(
    const float* __restrict__ v, const float* __restrict__ mf,
    const float* __restrict__ attn,
    __nv_bfloat16* __restrict__ tokhi, __nv_bfloat16* __restrict__ toklo)
{
    __shared__ __align__(16) float At[1024];
    __shared__ float Vs[128][33];
    __shared__ float Ms[32][128];
    int bh = blockIdx.y;
    int b = bh >> 3, h = bh & 7;
    int n0 = blockIdx.x * 128;
    int tid = threadIdx.x;
    #pragma unroll
    for (int i = 0; i < 8; i++) At[tid + i * 128] = attn[(size_t)bh * 1024 + tid + i * 128];
    #pragma unroll
    for (int i = 0; i < 32; i++) {
        int idx = tid + i * 128;
        int tk = idx >> 5, j = idx & 31;
        Vs[tk][j] = v[((size_t)b * NN + n0 + tk) * CC + h * DD + j];
        int jm = idx >> 7, tm = idx & 127;
        Ms[jm][tm] = mf[(size_t)(h * DD + jm) * NN + n0 + tm];
    }
    __syncthreads();
    int t = tid;
    float vm[32];
    #pragma unroll
    for (int j = 0; j < 32; j++) vm[j] = Vs[t][j] * Ms[j][t];
    size_t obase = ((size_t)b * NN + n0 + t) * CC + h * DD;
    const float4* At4 = (const float4*)At;
    #pragma unroll
    for (int i = 0; i < 32; i++) {
        float o = 0.f;
        #pragma unroll
        for (int jv = 0; jv < 8; jv++) {
            float4 w = At4[i * 8 + jv];
            o = fmaf(w.x, vm[jv * 4 + 0], o);
            o = fmaf(w.y, vm[jv * 4 + 1], o);
            o = fmaf(w.z, vm[jv * 4 + 2], o);
            o = fmaf(w.w, vm[jv * 4 + 3], o);
        }
        __nv_bfloat16 hi = __float2bfloat16(o);
        tokhi[obase + i] = hi;
        toklo[obase + i] = __float2bfloat16(o - __bfloat162float(hi));
    }
}

// ---------------- depthwise 3x3 (pad=1), rolling register window -------------------
__global__ __launch_bounds__(256) void dw3x3_k(
    const float* __restrict__ in, const float* __restrict__ w9,
    float* __restrict__ out, int mode)
{
    __shared__ float ws[9 * CC];
    int c = threadIdx.x;
    int y = blockIdx.x, b = blockIdx.y;
    #pragma unroll
    for (int i = 0; i < 9; i++) ws[c + i * CC] = w9[c + i * CC];
    __syncthreads();
    float wv[9];
    #pragma unroll
    for (int t = 0; t < 9; t++) wv[t] = ws[c * 9 + t];
    const size_t base = (size_t)b * NN * CC + c;
    float a[3][3];
    #pragma unroll
    for (int r = 0; r < 3; r++) {
        int yy = y - 1 + r;
        bool yok = (yy >= 0 && yy < HH);
        a[r][0] = 0.f;
        a[r][1] = yok ? in[base + (size_t)(yy * WW + 0) * CC] : 0.f;
        a[r][2] = yok ? in[base + (size_t)(yy * WW + 1) * CC] : 0.f;
    }
    for (int x = 0; x < WW; x++) {
        float acc = 0.f;
        #pragma unroll
        for (int r = 0; r < 3; r++)
            #pragma unroll
            for (int k2 = 0; k2 < 3; k2++)
                acc = fmaf(wv[r * 3 + k2], a[r][k2], acc);
        size_t o = base + (size_t)(y * WW + x) * CC;
        if (mode == 0) {
            acc = 0.5f * acc * (1.f + erff(acc * 0.70710678118654752f));
            out[o] = acc;
        } else {
            out[o] += acc;
        }
        int xn = x + 2;
        bool xok = (xn < WW);
        #pragma unroll
        for (int r = 0; r < 3; r++) {
            int yy = y - 1 + r;
            bool ok = xok && (yy >= 0 && yy < HH);
            a[r][0] = a[r][1];
            a[r][1] = a[r][2];
            a[r][2] = ok ? in[base + (size_t)(yy * WW + xn) * CC] : 0.f;
        }
    }
}

// ================================= launch ==========================================
extern "C" void kernel_launch(void* const* d_in, const int* in_sizes, int n_in,
                              void* d_out, int out_size)
{
    const float* x      = (const float*)d_in[0];
    const float* mask   = (const float*)d_in[1];
    const float* wq     = (const float*)d_in[2];
    const float* wk     = (const float*)d_in[3];
    const float* wv     = (const float*)d_in[4];
    const float* rescale= (const float*)d_in[5];
    const float* wproj  = (const float*)d_in[6];
    const float* bproj  = (const float*)d_in[7];
    const float* mg_w1  = (const float*)d_in[8];
    const float* mg_b1  = (const float*)d_in[9];
    const float* mg_w2  = (const float*)d_in[10];
    const float* mg_b2  = (const float*)d_in[11];
    const float* mg_dw  = (const float*)d_in[12];
    const float* mg_db  = (const float*)d_in[13];
    const float* be_w1  = (const float*)d_in[14];
    const float* be_w2  = (const float*)d_in[15];
    float* out = (float*)d_out;

    float *q, *k, *v, *y1, *m1, *m2, *mf, *npq, *npk, *gnorm, *gp, *attn;
    __nv_bfloat16 *xhi, *xlo, *tokhi, *toklo, *wqkvh, *wqkvl, *wph, *wpl;
    __nv_bfloat16 *w1h, *w1l, *w2h, *w2l, *mTh, *mTl, *m1th, *m1tl;
    cudaGetSymbolAddress((void**)&q,    g_q);
    cudaGetSymbolAddress((void**)&k,    g_k);
    cudaGetSymbolAddress((void**)&v,    g_v);
    cudaGetSymbolAddress((void**)&y1,   g_y1);
    cudaGetSymbolAddress((void**)&m1,   g_m1);
    cudaGetSymbolAddress((void**)&m2,   g_m2);
    cudaGetSymbolAddress((void**)&mf,   g_mf);
    cudaGetSymbolAddress((void**)&npq,  g_npq);
    cudaGetSymbolAddress((void**)&npk,  g_npk);
    cudaGetSymbolAddress((void**)&gnorm,g_norm);
    cudaGetSymbolAddress((void**)&gp,   g_gp);
    cudaGetSymbolAddress((void**)&attn, g_attn);
    cudaGetSymbolAddress((void**)&xhi,  g_xhi);
    cudaGetSymbolAddress((void**)&xlo,  g_xlo);
    cudaGetSymbolAddress((void**)&tokhi,g_tokhi);
    cudaGetSymbolAddress((void**)&toklo,g_toklo);
    cudaGetSymbolAddress((void**)&wqkvh,g_wqkvh);
    cudaGetSymbolAddress((void**)&wqkvl,g_wqkvl);
    cudaGetSymbolAddress((void**)&wph,  g_wph);
    cudaGetSymbolAddress((void**)&wpl,  g_wpl);
    cudaGetSymbolAddress((void**)&w1h,  g_w1h);
    cudaGetSymbolAddress((void**)&w1l,  g_w1l);
    cudaGetSymbolAddress((void**)&w2h,  g_w2h);
    cudaGetSymbolAddress((void**)&w2l,  g_w2l);
    cudaGetSymbolAddress((void**)&mTh,  g_mTh);
    cudaGetSymbolAddress((void**)&mTl,  g_mTl);
    cudaGetSymbolAddress((void**)&m1th, g_m1th);
    cudaGetSymbolAddress((void**)&m1tl, g_m1tl);

    const int MMASMEM = 8 * CHEL * 2;   // 81920 bytes
    cudaFuncSetAttribute(mmagemm2, cudaFuncAttributeMaxDynamicSharedMemorySize, MMASMEM);

    // prep needed for qkv, then qkv as 4th launch (ncu capture target)
    split_bf16<<<(MROWS * CC) / 1024, 256>>>(x, xhi, xlo);          // 1
    pack_wqkv<<<768, 256>>>(wq, wk, wv, wqkvh, wqkvl);              // 2
    pack_w1<<<256, 256>>>(wproj, wph, wpl);                         // 3
    mmagemm2<<<dim3(6, MROWS / 128), 512, MMASMEM>>>(               // 4 <- profiled
        xhi, xlo, wqkvh, wqkvl, q, k, v, nullptr, 0, 0, 256);

    // mask-path prep + GEMMs
    split_bf16<<<(CC * CC) / 1024, 256>>>(mg_w1, w1h, w1l);
    split_bf16<<<(CC * CC) / 1024, 256>>>(mg_w2, w2h, w2l);
    tr_split<<<dim3(NN / 32, CC / 32), dim3(32, 8)>>>(mask, CC, NN, mTh, mTl);
    mmagemm2<<<dim3(NN / 128, CC / 128), 512, MMASMEM>>>(
        w1h, w1l, mTh, mTl, m1, nullptr, nullptr, mg_b1, 2, 1, NN);
    tr_split<<<dim3(NN / 32, CC / 32), dim3(32, 8)>>>(m1, CC, NN, m1th, m1tl);
    mmagemm2<<<dim3(NN / 128, CC / 128), 512, MMASMEM>>>(
        w2h, w2l, m1th, m1tl, m2, nullptr, nullptr, mg_b2, 2, 1, NN);
    mask5<<<dim3(HH, CC), 128>>>(m2, m1, mg_dw, mg_db, mf);

    // norms + gram + softmax
    norm_part<<<dim3(64, BB), 256>>>(q, k, npq, npk);
    norm_reduce<<<dim3(BB, 2), 256>>>(npq, npk, gnorm);
    gram_part<<<dim3(16, BB * HEADS), 256>>>(q, k, gp);
    softmax_k<<<4, 256>>>(gp, gnorm, rescale, attn);

    // out_tok = attn @ (v * mask_emb) -> bf16 hi/lo
    av_k<<<dim3(NN / 128, BB * HEADS), 128>>>(v, mf, attn, tokhi, toklo);

    // projection into d_out
    mmagemm2<<<dim3(2, MROWS / 128), 512, MMASMEM>>>(
        tokhi, toklo, wph, wpl, out, out, out, bproj, 1, 0, 256);

    // band_emb: dw3x3 -> GELU -> dw3x3, added into d_out
    dw3x3_k<<<dim3(HH, BB), 256>>>(v, be_w1, y1, 0);
    dw3x3_k<<<dim3(HH, BB), 256>>>(y1, be_w2, out, 1);
}